// round 1
// baseline (speedup 1.0000x reference)
#include <cuda_runtime.h>
#include <cuda_bf16.h>

#define BT   4096
#define DIM  1024
#define NEXP 8
#define HID  2048

// Scratch (device globals: allocation-free per harness rules)
__device__ int   g_cnt[NEXP];
__device__ int   g_list[NEXP][BT];
__device__ float g_h[(size_t)BT * HID];   // 33.5 MB intermediate h, indexed by original token

// ---------------------------------------------------------------------------
// Kernel 0: zero the per-expert counters
// ---------------------------------------------------------------------------
__global__ void init_kernel() {
    if (threadIdx.x < NEXP) g_cnt[threadIdx.x] = 0;
}

// ---------------------------------------------------------------------------
// Kernel 1: gating logits + argmax (one warp per token), scatter into lists
// ---------------------------------------------------------------------------
__global__ void gate_kernel(const float* __restrict__ x,
                            const float* __restrict__ gw) {
    int warp = (blockIdx.x * blockDim.x + threadIdx.x) >> 5;
    int lane = threadIdx.x & 31;
    if (warp >= BT) return;
    const float* xr = x + (size_t)warp * DIM;

    float acc[NEXP];
#pragma unroll
    for (int e = 0; e < NEXP; e++) acc[e] = 0.f;

    for (int d = lane; d < DIM; d += 32) {
        float xv = xr[d];
#pragma unroll
        for (int e = 0; e < NEXP; e++) acc[e] += xv * gw[e * DIM + d];
    }
#pragma unroll
    for (int e = 0; e < NEXP; e++) {
#pragma unroll
        for (int o = 16; o > 0; o >>= 1)
            acc[e] += __shfl_xor_sync(0xffffffffu, acc[e], o);
    }
    if (lane == 0) {
        int best = 0; float bv = acc[0];
#pragma unroll
        for (int e = 1; e < NEXP; e++)
            if (acc[e] > bv) { bv = acc[e]; best = e; }   // first-max ties like argmax
        int p = atomicAdd(&g_cnt[best], 1);
        g_list[best][p] = warp;
    }
}

// ---------------------------------------------------------------------------
// Kernel 2: h = silu(x @ gate_bank[e]) * (x @ up_bank[e]) for grouped tokens
// Tile: 128 tokens x 64 h-cols, K-tile 16, 256 threads, 8x4 micro per matrix
// ---------------------------------------------------------------------------
__global__ __launch_bounds__(256, 2)
void ffn1_kernel(const float* __restrict__ x,
                 const float* __restrict__ gate_bank,
                 const float* __restrict__ up_bank) {
    int e = blockIdx.z;
    int n = g_cnt[e];
    int row0 = blockIdx.y * 128;
    if (row0 >= n) return;
    int col0 = blockIdx.x * 64;

    const float* Bg = gate_bank + (size_t)e * DIM * HID;
    const float* Bu = up_bank   + (size_t)e * DIM * HID;

    __shared__ float As[16][128];
    __shared__ float Bgs[16][64];
    __shared__ float Bus[16][64];
    __shared__ int   toks[128];

    int tid = threadIdx.x;
    if (tid < 128) {
        int r = row0 + tid;
        toks[tid] = (r < n) ? g_list[e][r] : -1;
    }
    __syncthreads();

    float accg[8][4], accu[8][4];
#pragma unroll
    for (int i = 0; i < 8; i++)
#pragma unroll
        for (int j = 0; j < 4; j++) { accg[i][j] = 0.f; accu[i][j] = 0.f; }

    int ty = tid >> 4;      // 0..15 -> 8 rows each
    int tx = tid & 15;      // 0..15 -> 4 cols each

    for (int k0 = 0; k0 < DIM; k0 += 16) {
        // A tile: 128 rows x 16 k, gathered rows of x (2 float4 per thread)
#pragma unroll
        for (int i = 0; i < 2; i++) {
            int idx = tid * 2 + i;          // 0..511
            int r = idx >> 2;               // 0..127
            int v = idx & 3;                // float4 slot in the 16 k-floats
            int t = toks[r];
            float4 val = make_float4(0.f, 0.f, 0.f, 0.f);
            if (t >= 0)
                val = *(const float4*)(x + (size_t)t * DIM + k0 + v * 4);
            As[v * 4 + 0][r] = val.x;
            As[v * 4 + 1][r] = val.y;
            As[v * 4 + 2][r] = val.z;
            As[v * 4 + 3][r] = val.w;
        }
        // B tiles: 16 k-rows x 64 cols each (1 float4 per thread per matrix)
        {
            int r = tid >> 4;
            int c = (tid & 15) * 4;
            const float* pg = Bg + (size_t)(k0 + r) * HID + col0 + c;
            const float* pu = Bu + (size_t)(k0 + r) * HID + col0 + c;
            *(float4*)&Bgs[r][c] = *(const float4*)pg;
            *(float4*)&Bus[r][c] = *(const float4*)pu;
        }
        __syncthreads();

#pragma unroll
        for (int k = 0; k < 16; k++) {
            float a[8];
#pragma unroll
            for (int i = 0; i < 8; i++) a[i] = As[k][ty * 8 + i];
            float bg[4], bu[4];
#pragma unroll
            for (int j = 0; j < 4; j++) {
                bg[j] = Bgs[k][tx * 4 + j];
                bu[j] = Bus[k][tx * 4 + j];
            }
#pragma unroll
            for (int i = 0; i < 8; i++)
#pragma unroll
                for (int j = 0; j < 4; j++) {
                    accg[i][j] += a[i] * bg[j];
                    accu[i][j] += a[i] * bu[j];
                }
        }
        __syncthreads();
    }

    // epilogue: silu(a) * u -> g_h[token][col]
#pragma unroll
    for (int i = 0; i < 8; i++) {
        int r = ty * 8 + i;
        int t = toks[r];
        if (t < 0) continue;
        float* dst = g_h + (size_t)t * HID + col0 + tx * 4;
#pragma unroll
        for (int j = 0; j < 4; j++) {
            float a = accg[i][j];
            float u = accu[i][j];
            float s = 1.f / (1.f + __expf(-a));
            dst[j] = a * s * u;
        }
    }
}

// ---------------------------------------------------------------------------
// Kernel 3: y = h @ down_bank[e], scatter to out[token]
// Tile: 128 tokens x 64 d-cols, K = 2048
// ---------------------------------------------------------------------------
__global__ __launch_bounds__(256, 2)
void ffn2_kernel(const float* __restrict__ down_bank,
                 float* __restrict__ out) {
    int e = blockIdx.z;
    int n = g_cnt[e];
    int row0 = blockIdx.y * 128;
    if (row0 >= n) return;
    int col0 = blockIdx.x * 64;

    const float* Bd = down_bank + (size_t)e * HID * DIM;

    __shared__ float As[16][128];
    __shared__ float Bs[16][64];
    __shared__ int   toks[128];

    int tid = threadIdx.x;
    if (tid < 128) {
        int r = row0 + tid;
        toks[tid] = (r < n) ? g_list[e][r] : -1;
    }
    __syncthreads();

    float acc[8][4];
#pragma unroll
    for (int i = 0; i < 8; i++)
#pragma unroll
        for (int j = 0; j < 4; j++) acc[i][j] = 0.f;

    int ty = tid >> 4;
    int tx = tid & 15;

    for (int k0 = 0; k0 < HID; k0 += 16) {
#pragma unroll
        for (int i = 0; i < 2; i++) {
            int idx = tid * 2 + i;
            int r = idx >> 2;
            int v = idx & 3;
            int t = toks[r];
            float4 val = make_float4(0.f, 0.f, 0.f, 0.f);
            if (t >= 0)
                val = *(const float4*)(g_h + (size_t)t * HID + k0 + v * 4);
            As[v * 4 + 0][r] = val.x;
            As[v * 4 + 1][r] = val.y;
            As[v * 4 + 2][r] = val.z;
            As[v * 4 + 3][r] = val.w;
        }
        {
            int r = tid >> 4;
            int c = (tid & 15) * 4;
            const float* pb = Bd + (size_t)(k0 + r) * DIM + col0 + c;
            *(float4*)&Bs[r][c] = *(const float4*)pb;
        }
        __syncthreads();

#pragma unroll
        for (int k = 0; k < 16; k++) {
            float a[8];
#pragma unroll
            for (int i = 0; i < 8; i++) a[i] = As[k][ty * 8 + i];
            float b[4];
#pragma unroll
            for (int j = 0; j < 4; j++) b[j] = Bs[k][tx * 4 + j];
#pragma unroll
            for (int i = 0; i < 8; i++)
#pragma unroll
                for (int j = 0; j < 4; j++)
                    acc[i][j] += a[i] * b[j];
        }
        __syncthreads();
    }

#pragma unroll
    for (int i = 0; i < 8; i++) {
        int r = ty * 8 + i;
        int t = toks[r];
        if (t < 0) continue;
        float* dst = out + (size_t)t * DIM + col0 + tx * 4;
#pragma unroll
        for (int j = 0; j < 4; j++) dst[j] = acc[i][j];
    }
}

// ---------------------------------------------------------------------------
extern "C" void kernel_launch(void* const* d_in, const int* in_sizes, int n_in,
                              void* d_out, int out_size) {
    const float* x         = (const float*)d_in[0];
    const float* gate_w    = (const float*)d_in[1];
    const float* gate_bank = (const float*)d_in[2];
    const float* up_bank   = (const float*)d_in[3];
    const float* down_bank = (const float*)d_in[4];
    float* out = (float*)d_out;

    init_kernel<<<1, 32>>>();
    gate_kernel<<<BT / 4, 128>>>(x, gate_w);
    ffn1_kernel<<<dim3(HID / 64, BT / 128, NEXP), 256>>>(x, gate_bank, up_bank);
    ffn2_kernel<<<dim3(DIM / 64, BT / 128, NEXP), 256>>>(down_bank, out);
}

// round 4
// speedup vs baseline: 1.9325x; 1.9325x over previous
#include <cuda_runtime.h>
#include <cuda_bf16.h>
#include <cstdint>

#define BT   4096
#define DIM  1024
#define NEXP 8
#define HID  2048

// ---------------------------------------------------------------------------
// Device global scratch (allocation-free per harness rules)
// ---------------------------------------------------------------------------
__device__ int g_cnt[NEXP];
__device__ int g_list[NEXP][BT];
__device__ __align__(16) __nv_bfloat16 g_xh[(size_t)BT * DIM];
__device__ __align__(16) __nv_bfloat16 g_xl[(size_t)BT * DIM];
__device__ __align__(16) __nv_bfloat16 g_hh[(size_t)BT * HID];
__device__ __align__(16) __nv_bfloat16 g_hl[(size_t)BT * HID];
__device__ __align__(16) float g_a[(size_t)BT * HID];
__device__ __align__(16) float g_u[(size_t)BT * HID];
// Transposed weight banks, [E][N][K] K-major, bf16 hi/lo
__device__ __align__(16) __nv_bfloat16 g_Wgh[(size_t)NEXP * HID * DIM];
__device__ __align__(16) __nv_bfloat16 g_Wgl[(size_t)NEXP * HID * DIM];
__device__ __align__(16) __nv_bfloat16 g_Wuh[(size_t)NEXP * HID * DIM];
__device__ __align__(16) __nv_bfloat16 g_Wul[(size_t)NEXP * HID * DIM];
__device__ __align__(16) __nv_bfloat16 g_Wdh[(size_t)NEXP * DIM * HID];
__device__ __align__(16) __nv_bfloat16 g_Wdl[(size_t)NEXP * DIM * HID];

// ---------------------------------------------------------------------------
// Helpers
// ---------------------------------------------------------------------------
__device__ __forceinline__ uint32_t smem_to_u32(const void* smem_ptr) {
    uint32_t addr;
    asm("{ .reg .u64 tmp; cvta.to.shared.u64 tmp, %1; cvt.u32.u64 %0, tmp; }"
        : "=r"(addr) : "l"(smem_ptr));
    return addr;
}

__device__ __forceinline__ void cp16(uint32_t dst, const void* src, uint32_t sz) {
    asm volatile("cp.async.cg.shared.global [%0], [%1], 16, %2;\n"
                 :: "r"(dst), "l"(src), "r"(sz));
}
#define CP_COMMIT() asm volatile("cp.async.commit_group;\n" ::: "memory")
#define CP_WAIT1()  asm volatile("cp.async.wait_group 1;\n" ::: "memory")

__device__ __forceinline__ uint32_t ldb32(const __nv_bfloat16* p) {
    return *(const uint32_t*)p;
}

#define MMA_BF16(acc, a, b) \
    asm volatile("mma.sync.aligned.m16n8k16.row.col.f32.bf16.bf16.f32 " \
        "{%0,%1,%2,%3}, {%4,%5,%6,%7}, {%8,%9}, {%0,%1,%2,%3};" \
        : "+f"((acc)[0]), "+f"((acc)[1]), "+f"((acc)[2]), "+f"((acc)[3]) \
        : "r"((a)[0]), "r"((a)[1]), "r"((a)[2]), "r"((a)[3]), \
          "r"((b)[0]), "r"((b)[1]))

// ---------------------------------------------------------------------------
// Kernel 0: zero counters
// ---------------------------------------------------------------------------
__global__ void init_kernel() {
    if (threadIdx.x < NEXP) g_cnt[threadIdx.x] = 0;
}

// ---------------------------------------------------------------------------
// Kernel 1: gating (fp32, one warp/token) + scatter to expert lists
// ---------------------------------------------------------------------------
__global__ void gate_kernel(const float* __restrict__ x,
                            const float* __restrict__ gw) {
    int warp = (blockIdx.x * blockDim.x + threadIdx.x) >> 5;
    int lane = threadIdx.x & 31;
    if (warp >= BT) return;
    const float* xr = x + (size_t)warp * DIM;

    float acc[NEXP];
#pragma unroll
    for (int e = 0; e < NEXP; e++) acc[e] = 0.f;
    for (int d = lane; d < DIM; d += 32) {
        float xv = xr[d];
#pragma unroll
        for (int e = 0; e < NEXP; e++) acc[e] += xv * gw[e * DIM + d];
    }
#pragma unroll
    for (int e = 0; e < NEXP; e++) {
#pragma unroll
        for (int o = 16; o > 0; o >>= 1)
            acc[e] += __shfl_xor_sync(0xffffffffu, acc[e], o);
    }
    if (lane == 0) {
        int best = 0; float bv = acc[0];
#pragma unroll
        for (int e = 1; e < NEXP; e++)
            if (acc[e] > bv) { bv = acc[e]; best = e; }
        int p = atomicAdd(&g_cnt[best], 1);
        g_list[best][p] = warp;
    }
}

// ---------------------------------------------------------------------------
// Kernel 2: split x into bf16 hi/lo
// ---------------------------------------------------------------------------
__global__ void convert_x_kernel(const float* __restrict__ x) {
    int i = blockIdx.x * blockDim.x + threadIdx.x;   // over BT*DIM/4
    float4 v = ((const float4*)x)[i];
    __nv_bfloat16 h0 = __float2bfloat16(v.x), h1 = __float2bfloat16(v.y);
    __nv_bfloat16 h2 = __float2bfloat16(v.z), h3 = __float2bfloat16(v.w);
    __nv_bfloat16 l0 = __float2bfloat16(v.x - __bfloat162float(h0));
    __nv_bfloat16 l1 = __float2bfloat16(v.y - __bfloat162float(h1));
    __nv_bfloat16 l2 = __float2bfloat16(v.z - __bfloat162float(h2));
    __nv_bfloat16 l3 = __float2bfloat16(v.w - __bfloat162float(h3));
    ((__nv_bfloat162*)g_xh)[2 * i + 0] = __halves2bfloat162(h0, h1);
    ((__nv_bfloat162*)g_xh)[2 * i + 1] = __halves2bfloat162(h2, h3);
    ((__nv_bfloat162*)g_xl)[2 * i + 0] = __halves2bfloat162(l0, l1);
    ((__nv_bfloat162*)g_xl)[2 * i + 1] = __halves2bfloat162(l2, l3);
}

// ---------------------------------------------------------------------------
// Kernel 3: transpose + split weights: in [E][rows][cols] -> out [E][cols][rows]
// ---------------------------------------------------------------------------
__global__ void transpose_split_kernel(const float* __restrict__ in, int which,
                                       int rows, int cols) {
    __nv_bfloat16 *oh, *ol;
    if (which == 0)      { oh = g_Wgh; ol = g_Wgl; }
    else if (which == 1) { oh = g_Wuh; ol = g_Wul; }
    else                 { oh = g_Wdh; ol = g_Wdl; }

    __shared__ float tile[32][33];
    size_t mat = (size_t)blockIdx.z * rows * cols;
    int c0 = blockIdx.x * 32, r0 = blockIdx.y * 32;
    int tx = threadIdx.x, ty = threadIdx.y;

#pragma unroll
    for (int i = ty; i < 32; i += 8)
        tile[i][tx] = in[mat + (size_t)(r0 + i) * cols + c0 + tx];
    __syncthreads();
#pragma unroll
    for (int i = ty; i < 32; i += 8) {
        float v = tile[tx][i];
        __nv_bfloat16 h = __float2bfloat16(v);
        __nv_bfloat16 l = __float2bfloat16(v - __bfloat162float(h));
        size_t o = mat + (size_t)(c0 + i) * rows + r0 + tx;
        oh[o] = h;
        ol[o] = l;
    }
}

// ---------------------------------------------------------------------------
// Unified grouped GEMM, bf16 3-term split, mma.sync HMMA path.
// mode 0: a = x @ Wg   (A=g_xh/xl,  W=g_Wgh/gl, C=g_a,  K=DIM, N=HID)
// mode 1: u = x @ Wu   (A=g_xh/xl,  W=g_Wuh/ul, C=g_u,  K=DIM, N=HID)
// mode 2: y = h @ Wd   (A=g_hh/hl,  W=g_Wdh/dl, C=out,  K=HID, N=DIM)
// CTA: 128 tokens x 128 cols; 8 warps, warp tile 64x32; K-chunk 32, 2 stages.
// ---------------------------------------------------------------------------
#define LDT        40                       // padded halves per smem row
#define MAT_H      (128 * LDT)              // 5120 halves per matrix
#define STG_H      (4 * MAT_H)              // 20480 halves per stage
#define SMEM_GEMM  (2 * STG_H * 2 + 512)    // bytes

__global__ __launch_bounds__(256, 1)
void gemm3_kernel(int mode, float* __restrict__ Cout) {
    extern __shared__ __align__(16) __nv_bfloat16 sm[];

    const __nv_bfloat16 *Agh, *Agl, *Wbh, *Wbl;
    float* C;
    int K, Ntot, ldc;
    if (mode == 0) {
        Agh = g_xh; Agl = g_xl; Wbh = g_Wgh; Wbl = g_Wgl;
        C = g_a; K = DIM; Ntot = HID; ldc = HID;
    } else if (mode == 1) {
        Agh = g_xh; Agl = g_xl; Wbh = g_Wuh; Wbl = g_Wul;
        C = g_u; K = DIM; Ntot = HID; ldc = HID;
    } else {
        Agh = g_hh; Agl = g_hl; Wbh = g_Wdh; Wbl = g_Wdl;
        C = Cout; K = HID; Ntot = DIM; ldc = DIM;
    }

    const int e = blockIdx.z;
    const int cnt = g_cnt[e];
    const int row0 = blockIdx.x * 128;
    if (row0 >= cnt) return;
    const int col0 = blockIdx.y * 128;
    const int tid = threadIdx.x;
    const int lane = tid & 31;
    const int wid = tid >> 5;
    const int wm = (wid >> 2) * 64;
    const int wn = (wid & 3) * 32;

    int* toks = (int*)(sm + 2 * STG_H);
    if (tid < 128) {
        int r = row0 + tid;
        toks[tid] = (r < cnt) ? g_list[e][r] : -1;
    }
    __syncthreads();

    const __nv_bfloat16* Wh = Wbh + ((size_t)e * Ntot + col0) * (size_t)K;
    const __nv_bfloat16* Wl = Wbl + ((size_t)e * Ntot + col0) * (size_t)K;
    const uint32_t sbase = smem_to_u32(sm);

    // token row pointers for this thread's two load rows (idx = tid, tid+256)
    int r_0 = tid >> 2,            s_0 = tid & 3;
    int r_1 = (tid + 256) >> 2,    s_1 = (tid + 256) & 3;
    int t_0 = toks[r_0], t_1 = toks[r_1];
    const __nv_bfloat16* a0h = Agh + (size_t)(t_0 < 0 ? 0 : t_0) * K + s_0 * 8;
    const __nv_bfloat16* a0l = Agl + (size_t)(t_0 < 0 ? 0 : t_0) * K + s_0 * 8;
    const __nv_bfloat16* a1h = Agh + (size_t)(t_1 < 0 ? 0 : t_1) * K + s_1 * 8;
    const __nv_bfloat16* a1l = Agl + (size_t)(t_1 < 0 ? 0 : t_1) * K + s_1 * 8;
    uint32_t sz0 = (t_0 >= 0) ? 16u : 0u;
    uint32_t sz1 = (t_1 >= 0) ? 16u : 0u;
    uint32_t dA0 = (uint32_t)(r_0 * (LDT * 2) + s_0 * 16);
    uint32_t dA1 = (uint32_t)(r_1 * (LDT * 2) + s_1 * 16);
    const __nv_bfloat16* w0h = Wh + (size_t)r_0 * K + s_0 * 8;
    const __nv_bfloat16* w0l = Wl + (size_t)r_0 * K + s_0 * 8;
    const __nv_bfloat16* w1h = Wh + (size_t)r_1 * K + s_1 * 8;
    const __nv_bfloat16* w1l = Wl + (size_t)r_1 * K + s_1 * 8;

    float acc[4][4][4];
#pragma unroll
    for (int m = 0; m < 4; m++)
#pragma unroll
        for (int n = 0; n < 4; n++)
#pragma unroll
            for (int r = 0; r < 4; r++) acc[m][n][r] = 0.f;

    const int NK = K >> 5;

    // prologue: load chunk 0 into stage 0
    {
        uint32_t sb = sbase;
        cp16(sb + dA0,                 a0h, sz0);
        cp16(sb + dA1,                 a1h, sz1);
        cp16(sb + MAT_H * 2 + dA0,     a0l, sz0);
        cp16(sb + MAT_H * 2 + dA1,     a1l, sz1);
        cp16(sb + MAT_H * 4 + dA0,     w0h, 16);
        cp16(sb + MAT_H * 4 + dA1,     w1h, 16);
        cp16(sb + MAT_H * 6 + dA0,     w0l, 16);
        cp16(sb + MAT_H * 6 + dA1,     w1l, 16);
        CP_COMMIT();
    }

    const int lr = lane >> 2;
    const int lk = (lane & 3) * 2;

    for (int i = 0; i < NK; i++) {
        if (i + 1 < NK) {
            int koff = (i + 1) * 32;
            uint32_t sb = sbase + ((i + 1) & 1) * (STG_H * 2);
            cp16(sb + dA0,             a0h + koff, sz0);
            cp16(sb + dA1,             a1h + koff, sz1);
            cp16(sb + MAT_H * 2 + dA0, a0l + koff, sz0);
            cp16(sb + MAT_H * 2 + dA1, a1l + koff, sz1);
            cp16(sb + MAT_H * 4 + dA0, w0h + koff, 16);
            cp16(sb + MAT_H * 4 + dA1, w1h + koff, 16);
            cp16(sb + MAT_H * 6 + dA0, w0l + koff, 16);
            cp16(sb + MAT_H * 6 + dA1, w1l + koff, 16);
        }
        CP_COMMIT();
        CP_WAIT1();
        __syncthreads();

        const __nv_bfloat16* Sa  = sm + (i & 1) * STG_H;
        const __nv_bfloat16* SaL = Sa + MAT_H;
        const __nv_bfloat16* Sb  = Sa + 2 * MAT_H;
        const __nv_bfloat16* SbL = Sa + 3 * MAT_H;

#pragma unroll
        for (int ks = 0; ks < 32; ks += 16) {
            uint32_t ah[4][4], al[4][4];
#pragma unroll
            for (int m = 0; m < 4; m++) {
                const __nv_bfloat16* p = Sa + (wm + m * 16 + lr) * LDT + ks + lk;
                ah[m][0] = ldb32(p);
                ah[m][1] = ldb32(p + 8 * LDT);
                ah[m][2] = ldb32(p + 8);
                ah[m][3] = ldb32(p + 8 * LDT + 8);
                const __nv_bfloat16* q = SaL + (wm + m * 16 + lr) * LDT + ks + lk;
                al[m][0] = ldb32(q);
                al[m][1] = ldb32(q + 8 * LDT);
                al[m][2] = ldb32(q + 8);
                al[m][3] = ldb32(q + 8 * LDT + 8);
            }
            uint32_t bh[4][2], bl[4][2];
#pragma unroll
            for (int n = 0; n < 4; n++) {
                const __nv_bfloat16* p = Sb + (wn + n * 8 + lr) * LDT + ks + lk;
                bh[n][0] = ldb32(p);
                bh[n][1] = ldb32(p + 8);
                const __nv_bfloat16* q = SbL + (wn + n * 8 + lr) * LDT + ks + lk;
                bl[n][0] = ldb32(q);
                bl[n][1] = ldb32(q + 8);
            }
#pragma unroll
            for (int m = 0; m < 4; m++)
#pragma unroll
                for (int n = 0; n < 4; n++) MMA_BF16(acc[m][n], ah[m], bh[n]);
#pragma unroll
            for (int m = 0; m < 4; m++)
#pragma unroll
                for (int n = 0; n < 4; n++) MMA_BF16(acc[m][n], al[m], bh[n]);
#pragma unroll
            for (int m = 0; m < 4; m++)
#pragma unroll
                for (int n = 0; n < 4; n++) MMA_BF16(acc[m][n], ah[m], bl[n]);
        }
        __syncthreads();
    }

    // epilogue: scatter fp32 to C rows by token
#pragma unroll
    for (int m = 0; m < 4; m++) {
        int r_ = wm + m * 16 + lr;
        int t0 = toks[r_];
        int t1 = toks[r_ + 8];
#pragma unroll
        for (int n = 0; n < 4; n++) {
            int c = col0 + wn + n * 8 + lk;
            if (t0 >= 0) {
                float2 v = make_float2(acc[m][n][0], acc[m][n][1]);
                *(float2*)(C + (size_t)t0 * ldc + c) = v;
            }
            if (t1 >= 0) {
                float2 v = make_float2(acc[m][n][2], acc[m][n][3]);
                *(float2*)(C + (size_t)t1 * ldc + c) = v;
            }
        }
    }
}

// ---------------------------------------------------------------------------
// Elementwise: h = silu(a)*u, split to bf16 hi/lo
// ---------------------------------------------------------------------------
__global__ void silu_split_kernel() {
    int i = blockIdx.x * blockDim.x + threadIdx.x;   // over BT*HID/4
    float4 a4 = ((const float4*)g_a)[i];
    float4 u4 = ((const float4*)g_u)[i];
    float h0 = a4.x * u4.x / (1.f + __expf(-a4.x));
    float h1 = a4.y * u4.y / (1.f + __expf(-a4.y));
    float h2 = a4.z * u4.z / (1.f + __expf(-a4.z));
    float h3 = a4.w * u4.w / (1.f + __expf(-a4.w));
    __nv_bfloat16 b0 = __float2bfloat16(h0), b1 = __float2bfloat16(h1);
    __nv_bfloat16 b2 = __float2bfloat16(h2), b3 = __float2bfloat16(h3);
    __nv_bfloat16 l0 = __float2bfloat16(h0 - __bfloat162float(b0));
    __nv_bfloat16 l1 = __float2bfloat16(h1 - __bfloat162float(b1));
    __nv_bfloat16 l2 = __float2bfloat16(h2 - __bfloat162float(b2));
    __nv_bfloat16 l3 = __float2bfloat16(h3 - __bfloat162float(b3));
    ((__nv_bfloat162*)g_hh)[2 * i + 0] = __halves2bfloat162(b0, b1);
    ((__nv_bfloat162*)g_hh)[2 * i + 1] = __halves2bfloat162(b2, b3);
    ((__nv_bfloat162*)g_hl)[2 * i + 0] = __halves2bfloat162(l0, l1);
    ((__nv_bfloat162*)g_hl)[2 * i + 1] = __halves2bfloat162(l2, l3);
}

// ---------------------------------------------------------------------------
extern "C" void kernel_launch(void* const* d_in, const int* in_sizes, int n_in,
                              void* d_out, int out_size) {
    const float* x         = (const float*)d_in[0];
    const float* gate_w    = (const float*)d_in[1];
    const float* gate_bank = (const float*)d_in[2];
    const float* up_bank   = (const float*)d_in[3];
    const float* down_bank = (const float*)d_in[4];
    float* out = (float*)d_out;

    cudaFuncSetAttribute(gemm3_kernel,
                         cudaFuncAttributeMaxDynamicSharedMemorySize, SMEM_GEMM);

    init_kernel<<<1, 32>>>();
    convert_x_kernel<<<(BT * DIM / 4) / 256, 256>>>(x);
    dim3 tb(32, 8);
    transpose_split_kernel<<<dim3(HID / 32, DIM / 32, NEXP), tb>>>(gate_bank, 0, DIM, HID);
    transpose_split_kernel<<<dim3(HID / 32, DIM / 32, NEXP), tb>>>(up_bank,   1, DIM, HID);
    transpose_split_kernel<<<dim3(DIM / 32, HID / 32, NEXP), tb>>>(down_bank, 2, HID, DIM);
    gate_kernel<<<BT / 4, 128>>>(x, gate_w);

    gemm3_kernel<<<dim3(BT / 128, HID / 128, NEXP), 256, SMEM_GEMM>>>(0, nullptr);
    gemm3_kernel<<<dim3(BT / 128, HID / 128, NEXP), 256, SMEM_GEMM>>>(1, nullptr);
    silu_split_kernel<<<(BT * HID / 4) / 256, 256>>>();
    gemm3_kernel<<<dim3(BT / 128, DIM / 128, NEXP), 256, SMEM_GEMM>>>(2, out);
}

// round 5
// speedup vs baseline: 2.2286x; 1.1532x over previous
#include <cuda_runtime.h>
#include <cuda_bf16.h>
#include <cstdint>

#define BT   4096
#define DIM  1024
#define NEXP 8
#define HID  2048

#define XSZ  ((size_t)BT * DIM)
#define HSZ  ((size_t)BT * HID)
#define WSZ  ((size_t)NEXP * HID * DIM)

// ---------------------------------------------------------------------------
// Device global scratch. hi at [0], lo at [+SIZE] (single symbol -> fewer regs)
// ---------------------------------------------------------------------------
__device__ int g_cnt[NEXP];
__device__ int g_list[NEXP][BT];
__device__ __align__(16) __nv_bfloat16 g_x2[2 * XSZ];
__device__ __align__(16) __nv_bfloat16 g_h2[2 * HSZ];
__device__ __align__(16) __nv_bfloat16 g_Wg2[2 * WSZ];
__device__ __align__(16) __nv_bfloat16 g_Wu2[2 * WSZ];
__device__ __align__(16) __nv_bfloat16 g_Wd2[2 * WSZ];

// ---------------------------------------------------------------------------
// Helpers
// ---------------------------------------------------------------------------
__device__ __forceinline__ uint32_t smem_to_u32(const void* smem_ptr) {
    uint32_t addr;
    asm("{ .reg .u64 tmp; cvta.to.shared.u64 tmp, %1; cvt.u32.u64 %0, tmp; }"
        : "=r"(addr) : "l"(smem_ptr));
    return addr;
}

__device__ __forceinline__ void cp16(uint32_t dst, const void* src, uint32_t sz) {
    asm volatile("cp.async.cg.shared.global [%0], [%1], 16, %2;\n"
                 :: "r"(dst), "l"(src), "r"(sz));
}
#define CP_COMMIT() asm volatile("cp.async.commit_group;\n" ::: "memory")
#define CP_WAIT1()  asm volatile("cp.async.wait_group 1;\n" ::: "memory")

__device__ __forceinline__ uint32_t ldb32(const __nv_bfloat16* p) {
    return *(const uint32_t*)p;
}

#define MMA_BF16(acc, a, b) \
    asm volatile("mma.sync.aligned.m16n8k16.row.col.f32.bf16.bf16.f32 " \
        "{%0,%1,%2,%3}, {%4,%5,%6,%7}, {%8,%9}, {%0,%1,%2,%3};" \
        : "+f"((acc)[0]), "+f"((acc)[1]), "+f"((acc)[2]), "+f"((acc)[3]) \
        : "r"((a)[0]), "r"((a)[1]), "r"((a)[2]), "r"((a)[3]), \
          "r"((b)[0]), "r"((b)[1]))

// ---------------------------------------------------------------------------
// Kernel 0: zero counters
// ---------------------------------------------------------------------------
__global__ void init_kernel() {
    if (threadIdx.x < NEXP) g_cnt[threadIdx.x] = 0;
}

// ---------------------------------------------------------------------------
// Kernel 1: fused x convert (bf16 hi/lo) + gating + scatter. One token/block.
// ---------------------------------------------------------------------------
__global__ __launch_bounds__(256) void gate_convert_kernel(
        const float* __restrict__ x, const float* __restrict__ gw) {
    __shared__ float red[8][8];
    __shared__ float logits[8];
    const int t = blockIdx.x;
    const int tid = threadIdx.x;
    const int lane = tid & 31, wid = tid >> 5;

    float4 v = ((const float4*)x)[(size_t)t * (DIM / 4) + tid];

    // split to bf16 hi/lo
    __nv_bfloat16 h0 = __float2bfloat16(v.x), h1 = __float2bfloat16(v.y);
    __nv_bfloat16 h2 = __float2bfloat16(v.z), h3 = __float2bfloat16(v.w);
    __nv_bfloat16 l0 = __float2bfloat16(v.x - __bfloat162float(h0));
    __nv_bfloat16 l1 = __float2bfloat16(v.y - __bfloat162float(h1));
    __nv_bfloat16 l2 = __float2bfloat16(v.z - __bfloat162float(h2));
    __nv_bfloat16 l3 = __float2bfloat16(v.w - __bfloat162float(h3));
    size_t o = (size_t)t * DIM + tid * 4;
    *(__nv_bfloat162*)(g_x2 + o)           = __halves2bfloat162(h0, h1);
    *(__nv_bfloat162*)(g_x2 + o + 2)       = __halves2bfloat162(h2, h3);
    *(__nv_bfloat162*)(g_x2 + XSZ + o)     = __halves2bfloat162(l0, l1);
    *(__nv_bfloat162*)(g_x2 + XSZ + o + 2) = __halves2bfloat162(l2, l3);

    // gating partial dots
    float acc[NEXP];
#pragma unroll
    for (int e = 0; e < NEXP; e++) {
        float4 g = ((const float4*)(gw + (size_t)e * DIM))[tid];
        acc[e] = v.x * g.x + v.y * g.y + v.z * g.z + v.w * g.w;
    }
#pragma unroll
    for (int e = 0; e < NEXP; e++) {
#pragma unroll
        for (int off = 16; off > 0; off >>= 1)
            acc[e] += __shfl_xor_sync(0xffffffffu, acc[e], off);
    }
    if (lane == 0) {
#pragma unroll
        for (int e = 0; e < NEXP; e++) red[wid][e] = acc[e];
    }
    __syncthreads();
    if (tid < 8) {
        float s = 0.f;
#pragma unroll
        for (int w = 0; w < 8; w++) s += red[w][tid];
        logits[tid] = s;
    }
    __syncthreads();
    if (tid == 0) {
        int best = 0; float bv = logits[0];
#pragma unroll
        for (int e = 1; e < NEXP; e++)
            if (logits[e] > bv) { bv = logits[e]; best = e; }
        int p = atomicAdd(&g_cnt[best], 1);
        g_list[best][p] = t;
    }
}

// ---------------------------------------------------------------------------
// Kernel 2: transpose + split weights: in [E][rows][cols] -> out [E][cols][rows]
// 64(row) x 32(col) fp32 tiles; hi/lo bf16 output, 128B-coalesced writes
// ---------------------------------------------------------------------------
__global__ __launch_bounds__(256) void transpose_split_kernel(
        const float* __restrict__ in, int which, int rows, int cols) {
    __nv_bfloat16* ob;
    if (which == 0)      ob = g_Wg2;
    else if (which == 1) ob = g_Wu2;
    else                 ob = g_Wd2;

    __shared__ float tile[64][33];
    size_t mat = (size_t)blockIdx.z * rows * cols;
    int c0 = blockIdx.x * 32, r0 = blockIdx.y * 64;
    int f = threadIdx.x;

#pragma unroll 4
    for (int idx = f; idx < 64 * 32; idx += 256) {
        int i = idx >> 5, c = idx & 31;
        tile[i][c] = in[mat + (size_t)(r0 + i) * cols + c0 + c];
    }
    __syncthreads();
#pragma unroll 4
    for (int idx = f; idx < 32 * 64; idx += 256) {
        int j = idx >> 6, k = idx & 63;
        float v = tile[k][j];
        __nv_bfloat16 h = __float2bfloat16(v);
        __nv_bfloat16 l = __float2bfloat16(v - __bfloat162float(h));
        size_t oo = mat + (size_t)(c0 + j) * rows + r0 + k;
        ob[oo] = h;
        ob[WSZ + oo] = l;
    }
}

// ---------------------------------------------------------------------------
// FFN1 fused: a = xWg, u = xWu, h = silu(a)*u -> bf16 hi/lo
// CTA 128 tok x 64 cols, 8 warps 32x32 (4m x 2n), K-chunk 32, 2-stage, occ 2
// smem halves layout per stage:
//   A_hi[128][40] @0, A_lo @5120, Bg_hi[64][40] @10240, Bg_lo @12800,
//   Bu_hi @15360, Bu_lo @17920 ; stage = 20480 halves
// ---------------------------------------------------------------------------
#define LDT    40
#define OFF_AL 5120
#define OFF_GH 10240
#define OFF_GL 12800
#define OFF_UH 15360
#define OFF_UL 17920
#define STG1   20480
#define SMEM1  (2 * STG1 * 2 + 512)

__global__ __launch_bounds__(256, 2) void ffn1_kernel() {
    extern __shared__ __align__(16) __nv_bfloat16 sm[];
    const int e = blockIdx.z;
    const int cnt = g_cnt[e];
    const int row0 = blockIdx.x * 128;
    if (row0 >= cnt) return;
    const int col0 = blockIdx.y * 64;
    const int tid = threadIdx.x, lane = tid & 31, wid = tid >> 5;
    const int wm = (wid & 3) * 32, wn = (wid >> 2) * 32;

    int* toks = (int*)(sm + 2 * STG1);
    if (tid < 128) {
        int r = row0 + tid;
        toks[tid] = (r < cnt) ? g_list[e][r] : -1;
    }
    __syncthreads();
    const uint32_t sbase = smem_to_u32(sm);

    // A loads: idx = tid, tid+256 -> r = idx>>2, s = idx&3
    int r0i = tid >> 2,          s0 = tid & 3;
    int r1i = (tid + 256) >> 2,  s1 = (tid + 256) & 3;
    int t0 = toks[r0i], t1 = toks[r1i];
    const __nv_bfloat16* a0 = g_x2 + (size_t)(t0 < 0 ? 0 : t0) * DIM + s0 * 8;
    const __nv_bfloat16* a1 = g_x2 + (size_t)(t1 < 0 ? 0 : t1) * DIM + s1 * 8;
    uint32_t sz0 = (t0 >= 0) ? 16u : 0u;
    uint32_t sz1 = (t1 >= 0) ? 16u : 0u;
    uint32_t dA0 = (uint32_t)(r0i * LDT + s0 * 8) * 2;
    uint32_t dA1 = (uint32_t)(r1i * LDT + s1 * 8) * 2;
    // B loads: r = tid>>2 (0..63), s = tid&3
    int rb = tid >> 2, sb_ = tid & 3;
    const __nv_bfloat16* wg = g_Wg2 + ((size_t)e * HID + col0 + rb) * DIM + sb_ * 8;
    const __nv_bfloat16* wu = g_Wu2 + ((size_t)e * HID + col0 + rb) * DIM + sb_ * 8;
    uint32_t dB = (uint32_t)(rb * LDT + sb_ * 8) * 2;

    float accg[2][4][4], accu[2][4][4];
#pragma unroll
    for (int mt = 0; mt < 2; mt++)
#pragma unroll
        for (int nt = 0; nt < 4; nt++)
#pragma unroll
            for (int j = 0; j < 4; j++) { accg[mt][nt][j] = 0.f; accu[mt][nt][j] = 0.f; }

    const int NK = DIM / 32;   // 32
    {
        uint32_t sb = sbase;
        cp16(sb + dA0, a0, sz0);
        cp16(sb + dA1, a1, sz1);
        cp16(sb + OFF_AL * 2 + dA0, a0 + XSZ, sz0);
        cp16(sb + OFF_AL * 2 + dA1, a1 + XSZ, sz1);
        cp16(sb + OFF_GH * 2 + dB, wg, 16);
        cp16(sb + OFF_GL * 2 + dB, wg + WSZ, 16);
        cp16(sb + OFF_UH * 2 + dB, wu, 16);
        cp16(sb + OFF_UL * 2 + dB, wu + WSZ, 16);
        CP_COMMIT();
    }

    const int lr = lane >> 2, lk = (lane & 3) * 2;

    for (int i = 0; i < NK; i++) {
        if (i + 1 < NK) {
            int ko = (i + 1) * 32;
            uint32_t sb = sbase + ((i + 1) & 1) * (STG1 * 2);
            cp16(sb + dA0, a0 + ko, sz0);
            cp16(sb + dA1, a1 + ko, sz1);
            cp16(sb + OFF_AL * 2 + dA0, a0 + XSZ + ko, sz0);
            cp16(sb + OFF_AL * 2 + dA1, a1 + XSZ + ko, sz1);
            cp16(sb + OFF_GH * 2 + dB, wg + ko, 16);
            cp16(sb + OFF_GL * 2 + dB, wg + WSZ + ko, 16);
            cp16(sb + OFF_UH * 2 + dB, wu + ko, 16);
            cp16(sb + OFF_UL * 2 + dB, wu + WSZ + ko, 16);
        }
        CP_COMMIT();
        CP_WAIT1();
        __syncthreads();

        const __nv_bfloat16* S = sm + (i & 1) * STG1;
#pragma unroll
        for (int ks = 0; ks < 32; ks += 16) {
            uint32_t ah[2][4], al[2][4];
#pragma unroll
            for (int mt = 0; mt < 2; mt++) {
                const __nv_bfloat16* p = S + (wm + mt * 16 + lr) * LDT + ks + lk;
                ah[mt][0] = ldb32(p);
                ah[mt][1] = ldb32(p + 8 * LDT);
                ah[mt][2] = ldb32(p + 8);
                ah[mt][3] = ldb32(p + 8 * LDT + 8);
                const __nv_bfloat16* q = p + OFF_AL;
                al[mt][0] = ldb32(q);
                al[mt][1] = ldb32(q + 8 * LDT);
                al[mt][2] = ldb32(q + 8);
                al[mt][3] = ldb32(q + 8 * LDT + 8);
            }
            {
                uint32_t bh[4][2], bl[4][2];
#pragma unroll
                for (int nt = 0; nt < 4; nt++) {
                    const __nv_bfloat16* p = S + OFF_GH + (wn + nt * 8 + lr) * LDT + ks + lk;
                    bh[nt][0] = ldb32(p);
                    bh[nt][1] = ldb32(p + 8);
                    bl[nt][0] = ldb32(p + (OFF_GL - OFF_GH));
                    bl[nt][1] = ldb32(p + (OFF_GL - OFF_GH) + 8);
                }
#pragma unroll
                for (int mt = 0; mt < 2; mt++)
#pragma unroll
                    for (int nt = 0; nt < 4; nt++) {
                        MMA_BF16(accg[mt][nt], ah[mt], bh[nt]);
                        MMA_BF16(accg[mt][nt], al[mt], bh[nt]);
                        MMA_BF16(accg[mt][nt], ah[mt], bl[nt]);
                    }
            }
            {
                uint32_t bh[4][2], bl[4][2];
#pragma unroll
                for (int nt = 0; nt < 4; nt++) {
                    const __nv_bfloat16* p = S + OFF_UH + (wn + nt * 8 + lr) * LDT + ks + lk;
                    bh[nt][0] = ldb32(p);
                    bh[nt][1] = ldb32(p + 8);
                    bl[nt][0] = ldb32(p + (OFF_UL - OFF_UH));
                    bl[nt][1] = ldb32(p + (OFF_UL - OFF_UH) + 8);
                }
#pragma unroll
                for (int mt = 0; mt < 2; mt++)
#pragma unroll
                    for (int nt = 0; nt < 4; nt++) {
                        MMA_BF16(accu[mt][nt], ah[mt], bh[nt]);
                        MMA_BF16(accu[mt][nt], al[mt], bh[nt]);
                        MMA_BF16(accu[mt][nt], ah[mt], bl[nt]);
                    }
            }
        }
        __syncthreads();
    }

    // epilogue: h = silu(a)*u -> bf16 hi/lo scatter
#pragma unroll
    for (int mt = 0; mt < 2; mt++) {
        int ra = wm + mt * 16 + lr;
        int ta = toks[ra], tb = toks[ra + 8];
#pragma unroll
        for (int nt = 0; nt < 4; nt++) {
            int col = col0 + wn + nt * 8 + lk;
            if (ta >= 0) {
                float a0v = accg[mt][nt][0], a1v = accg[mt][nt][1];
                float u0v = accu[mt][nt][0], u1v = accu[mt][nt][1];
                float hv0 = a0v * u0v / (1.f + __expf(-a0v));
                float hv1 = a1v * u1v / (1.f + __expf(-a1v));
                __nv_bfloat16 hh0 = __float2bfloat16(hv0), hh1 = __float2bfloat16(hv1);
                __nv_bfloat16 hl0 = __float2bfloat16(hv0 - __bfloat162float(hh0));
                __nv_bfloat16 hl1 = __float2bfloat16(hv1 - __bfloat162float(hh1));
                size_t oo = (size_t)ta * HID + col;
                *(__nv_bfloat162*)(g_h2 + oo)       = __halves2bfloat162(hh0, hh1);
                *(__nv_bfloat162*)(g_h2 + HSZ + oo) = __halves2bfloat162(hl0, hl1);
            }
            if (tb >= 0) {
                float a0v = accg[mt][nt][2], a1v = accg[mt][nt][3];
                float u0v = accu[mt][nt][2], u1v = accu[mt][nt][3];
                float hv0 = a0v * u0v / (1.f + __expf(-a0v));
                float hv1 = a1v * u1v / (1.f + __expf(-a1v));
                __nv_bfloat16 hh0 = __float2bfloat16(hv0), hh1 = __float2bfloat16(hv1);
                __nv_bfloat16 hl0 = __float2bfloat16(hv0 - __bfloat162float(hh0));
                __nv_bfloat16 hl1 = __float2bfloat16(hv1 - __bfloat162float(hh1));
                size_t oo = (size_t)tb * HID + col;
                *(__nv_bfloat162*)(g_h2 + oo)       = __halves2bfloat162(hh0, hh1);
                *(__nv_bfloat162*)(g_h2 + HSZ + oo) = __halves2bfloat162(hl0, hl1);
            }
        }
    }
}

// ---------------------------------------------------------------------------
// FFN2: out = h Wd (fp32 out). CTA 128 x 64, K = HID, same skeleton, occ 2
// smem: A_hi @0, A_lo @5120, B_hi @10240, B_lo @12800 ; stage 15360 halves
// ---------------------------------------------------------------------------
#define OFF2_AL 5120
#define OFF2_BH 10240
#define OFF2_BL 12800
#define STG2    15360
#define SMEM2   (2 * STG2 * 2 + 512)

__global__ __launch_bounds__(256, 2) void ffn2_kernel(float* __restrict__ out) {
    extern __shared__ __align__(16) __nv_bfloat16 sm[];
    const int e = blockIdx.z;
    const int cnt = g_cnt[e];
    const int row0 = blockIdx.x * 128;
    if (row0 >= cnt) return;
    const int col0 = blockIdx.y * 64;
    const int tid = threadIdx.x, lane = tid & 31, wid = tid >> 5;
    const int wm = (wid & 3) * 32, wn = (wid >> 2) * 32;

    int* toks = (int*)(sm + 2 * STG2);
    if (tid < 128) {
        int r = row0 + tid;
        toks[tid] = (r < cnt) ? g_list[e][r] : -1;
    }
    __syncthreads();
    const uint32_t sbase = smem_to_u32(sm);

    int r0i = tid >> 2,          s0 = tid & 3;
    int r1i = (tid + 256) >> 2,  s1 = (tid + 256) & 3;
    int t0 = toks[r0i], t1 = toks[r1i];
    const __nv_bfloat16* a0 = g_h2 + (size_t)(t0 < 0 ? 0 : t0) * HID + s0 * 8;
    const __nv_bfloat16* a1 = g_h2 + (size_t)(t1 < 0 ? 0 : t1) * HID + s1 * 8;
    uint32_t sz0 = (t0 >= 0) ? 16u : 0u;
    uint32_t sz1 = (t1 >= 0) ? 16u : 0u;
    uint32_t dA0 = (uint32_t)(r0i * LDT + s0 * 8) * 2;
    uint32_t dA1 = (uint32_t)(r1i * LDT + s1 * 8) * 2;
    int rb = tid >> 2, sb_ = tid & 3;
    const __nv_bfloat16* wd = g_Wd2 + ((size_t)e * DIM + col0 + rb) * HID + sb_ * 8;
    uint32_t dB = (uint32_t)(rb * LDT + sb_ * 8) * 2;

    float acc[2][4][4];
#pragma unroll
    for (int mt = 0; mt < 2; mt++)
#pragma unroll
        for (int nt = 0; nt < 4; nt++)
#pragma unroll
            for (int j = 0; j < 4; j++) acc[mt][nt][j] = 0.f;

    const int NK = HID / 32;   // 64
    {
        uint32_t sb = sbase;
        cp16(sb + dA0, a0, sz0);
        cp16(sb + dA1, a1, sz1);
        cp16(sb + OFF2_AL * 2 + dA0, a0 + HSZ, sz0);
        cp16(sb + OFF2_AL * 2 + dA1, a1 + HSZ, sz1);
        cp16(sb + OFF2_BH * 2 + dB, wd, 16);
        cp16(sb + OFF2_BL * 2 + dB, wd + WSZ, 16);
        CP_COMMIT();
    }

    const int lr = lane >> 2, lk = (lane & 3) * 2;

    for (int i = 0; i < NK; i++) {
        if (i + 1 < NK) {
            int ko = (i + 1) * 32;
            uint32_t sb = sbase + ((i + 1) & 1) * (STG2 * 2);
            cp16(sb + dA0, a0 + ko, sz0);
            cp16(sb + dA1, a1 + ko, sz1);
            cp16(sb + OFF2_AL * 2 + dA0, a0 + HSZ + ko, sz0);
            cp16(sb + OFF2_AL * 2 + dA1, a1 + HSZ + ko, sz1);
            cp16(sb + OFF2_BH * 2 + dB, wd + ko, 16);
            cp16(sb + OFF2_BL * 2 + dB, wd + WSZ + ko, 16);
        }
        CP_COMMIT();
        CP_WAIT1();
        __syncthreads();

        const __nv_bfloat16* S = sm + (i & 1) * STG2;
#pragma unroll
        for (int ks = 0; ks < 32; ks += 16) {
            uint32_t ah[2][4], al[2][4];
#pragma unroll
            for (int mt = 0; mt < 2; mt++) {
                const __nv_bfloat16* p = S + (wm + mt * 16 + lr) * LDT + ks + lk;
                ah[mt][0] = ldb32(p);
                ah[mt][1] = ldb32(p + 8 * LDT);
                ah[mt][2] = ldb32(p + 8);
                ah[mt][3] = ldb32(p + 8 * LDT + 8);
                const __nv_bfloat16* q = p + OFF2_AL;
                al[mt][0] = ldb32(q);
                al[mt][1] = ldb32(q + 8 * LDT);
                al[mt][2] = ldb32(q + 8);
                al[mt][3] = ldb32(q + 8 * LDT + 8);
            }
            uint32_t bh[4][2], bl[4][2];
#pragma unroll
            for (int nt = 0; nt < 4; nt++) {
                const __nv_bfloat16* p = S + OFF2_BH + (wn + nt * 8 + lr) * LDT + ks + lk;
                bh[nt][0] = ldb32(p);
                bh[nt][1] = ldb32(p + 8);
                bl[nt][0] = ldb32(p + (OFF2_BL - OFF2_BH));
                bl[nt][1] = ldb32(p + (OFF2_BL - OFF2_BH) + 8);
            }
#pragma unroll
            for (int mt = 0; mt < 2; mt++)
#pragma unroll
                for (int nt = 0; nt < 4; nt++) {
                    MMA_BF16(acc[mt][nt], ah[mt], bh[nt]);
                    MMA_BF16(acc[mt][nt], al[mt], bh[nt]);
                    MMA_BF16(acc[mt][nt], ah[mt], bl[nt]);
                }
        }
        __syncthreads();
    }

#pragma unroll
    for (int mt = 0; mt < 2; mt++) {
        int ra = wm + mt * 16 + lr;
        int ta = toks[ra], tb = toks[ra + 8];
#pragma unroll
        for (int nt = 0; nt < 4; nt++) {
            int col = col0 + wn + nt * 8 + lk;
            if (ta >= 0)
                *(float2*)(out + (size_t)ta * DIM + col) =
                    make_float2(acc[mt][nt][0], acc[mt][nt][1]);
            if (tb >= 0)
                *(float2*)(out + (size_t)tb * DIM + col) =
                    make_float2(acc[mt][nt][2], acc[mt][nt][3]);
        }
    }
}

// ---------------------------------------------------------------------------
extern "C" void kernel_launch(void* const* d_in, const int* in_sizes, int n_in,
                              void* d_out, int out_size) {
    const float* x         = (const float*)d_in[0];
    const float* gate_w    = (const float*)d_in[1];
    const float* gate_bank = (const float*)d_in[2];
    const float* up_bank   = (const float*)d_in[3];
    const float* down_bank = (const float*)d_in[4];
    float* out = (float*)d_out;

    cudaFuncSetAttribute(ffn1_kernel,
                         cudaFuncAttributeMaxDynamicSharedMemorySize, SMEM1);
    cudaFuncSetAttribute(ffn2_kernel,
                         cudaFuncAttributeMaxDynamicSharedMemorySize, SMEM2);

    init_kernel<<<1, 32>>>();
    gate_convert_kernel<<<BT, 256>>>(x, gate_w);
    transpose_split_kernel<<<dim3(HID / 32, DIM / 64, NEXP), 256>>>(gate_bank, 0, DIM, HID);
    transpose_split_kernel<<<dim3(HID / 32, DIM / 64, NEXP), 256>>>(up_bank,   1, DIM, HID);
    transpose_split_kernel<<<dim3(DIM / 32, HID / 64, NEXP), 256>>>(down_bank, 2, HID, DIM);

    ffn1_kernel<<<dim3(BT / 128, HID / 64, NEXP), 256, SMEM1>>>();
    ffn2_kernel<<<dim3(BT / 128, DIM / 64, NEXP), 256, SMEM2>>>(out);
}

// round 6
// speedup vs baseline: 2.6958x; 1.2096x over previous
#include <cuda_runtime.h>
#include <cuda_bf16.h>
#include <cstdint>

#define BT   4096
#define DIM  1024
#define NEXP 8
#define HID  2048

#define XSZ  ((size_t)BT * DIM)
#define HSZ  ((size_t)BT * HID)
#define WSZ  ((size_t)NEXP * HID * DIM)

// ---------------------------------------------------------------------------
// Device global scratch. hi at [0], lo at [+SIZE]
// Weights kept in NATIVE orientation (gate/up: [E][D][H], down: [E][H][D]);
// ldmatrix.trans handles the transpose at fragment-load time.
// ---------------------------------------------------------------------------
__device__ int g_cnt[NEXP];
__device__ int g_list[NEXP][BT];
__device__ __align__(16) __nv_bfloat16 g_x2[2 * XSZ];
__device__ __align__(16) __nv_bfloat16 g_h2[2 * HSZ];
__device__ __align__(16) __nv_bfloat16 g_Wg2[2 * WSZ];
__device__ __align__(16) __nv_bfloat16 g_Wu2[2 * WSZ];
__device__ __align__(16) __nv_bfloat16 g_Wd2[2 * WSZ];

// ---------------------------------------------------------------------------
// Helpers
// ---------------------------------------------------------------------------
__device__ __forceinline__ uint32_t smem_to_u32(const void* smem_ptr) {
    uint32_t addr;
    asm("{ .reg .u64 tmp; cvta.to.shared.u64 tmp, %1; cvt.u32.u64 %0, tmp; }"
        : "=r"(addr) : "l"(smem_ptr));
    return addr;
}

__device__ __forceinline__ void cp16(uint32_t dst, const void* src, uint32_t sz) {
    asm volatile("cp.async.cg.shared.global [%0], [%1], 16, %2;\n"
                 :: "r"(dst), "l"(src), "r"(sz));
}
#define CP_COMMIT() asm volatile("cp.async.commit_group;\n" ::: "memory")
#define CP_WAIT1()  asm volatile("cp.async.wait_group 1;\n" ::: "memory")

__device__ __forceinline__ void ldsm_x4(uint32_t* r, uint32_t addr) {
    asm volatile("ldmatrix.sync.aligned.m8n8.x4.shared.b16 {%0,%1,%2,%3}, [%4];"
        : "=r"(r[0]), "=r"(r[1]), "=r"(r[2]), "=r"(r[3]) : "r"(addr));
}
__device__ __forceinline__ void ldsm_x4t(uint32_t* r, uint32_t addr) {
    asm volatile("ldmatrix.sync.aligned.m8n8.x4.trans.shared.b16 {%0,%1,%2,%3}, [%4];"
        : "=r"(r[0]), "=r"(r[1]), "=r"(r[2]), "=r"(r[3]) : "r"(addr));
}

#define MMA_BF16(acc, a, b0, b1) \
    asm volatile("mma.sync.aligned.m16n8k16.row.col.f32.bf16.bf16.f32 " \
        "{%0,%1,%2,%3}, {%4,%5,%6,%7}, {%8,%9}, {%0,%1,%2,%3};" \
        : "+f"((acc)[0]), "+f"((acc)[1]), "+f"((acc)[2]), "+f"((acc)[3]) \
        : "r"((a)[0]), "r"((a)[1]), "r"((a)[2]), "r"((a)[3]), \
          "r"(b0), "r"(b1))

// ---------------------------------------------------------------------------
__global__ void init_kernel() {
    if (threadIdx.x < NEXP) g_cnt[threadIdx.x] = 0;
}

// ---------------------------------------------------------------------------
// Fused x convert (bf16 hi/lo) + gating + scatter. One token/block.
// ---------------------------------------------------------------------------
__global__ __launch_bounds__(256) void gate_convert_kernel(
        const float* __restrict__ x, const float* __restrict__ gw) {
    __shared__ float red[8][8];
    __shared__ float logits[8];
    const int t = blockIdx.x;
    const int tid = threadIdx.x;
    const int lane = tid & 31, wid = tid >> 5;

    float4 v = ((const float4*)x)[(size_t)t * (DIM / 4) + tid];

    __nv_bfloat16 h0 = __float2bfloat16(v.x), h1 = __float2bfloat16(v.y);
    __nv_bfloat16 h2 = __float2bfloat16(v.z), h3 = __float2bfloat16(v.w);
    __nv_bfloat16 l0 = __float2bfloat16(v.x - __bfloat162float(h0));
    __nv_bfloat16 l1 = __float2bfloat16(v.y - __bfloat162float(h1));
    __nv_bfloat16 l2 = __float2bfloat16(v.z - __bfloat162float(h2));
    __nv_bfloat16 l3 = __float2bfloat16(v.w - __bfloat162float(h3));
    size_t o = (size_t)t * DIM + tid * 4;
    *(__nv_bfloat162*)(g_x2 + o)           = __halves2bfloat162(h0, h1);
    *(__nv_bfloat162*)(g_x2 + o + 2)       = __halves2bfloat162(h2, h3);
    *(__nv_bfloat162*)(g_x2 + XSZ + o)     = __halves2bfloat162(l0, l1);
    *(__nv_bfloat162*)(g_x2 + XSZ + o + 2) = __halves2bfloat162(l2, l3);

    float acc[NEXP];
#pragma unroll
    for (int e = 0; e < NEXP; e++) {
        float4 g = ((const float4*)(gw + (size_t)e * DIM))[tid];
        acc[e] = v.x * g.x + v.y * g.y + v.z * g.z + v.w * g.w;
    }
#pragma unroll
    for (int e = 0; e < NEXP; e++) {
#pragma unroll
        for (int off = 16; off > 0; off >>= 1)
            acc[e] += __shfl_xor_sync(0xffffffffu, acc[e], off);
    }
    if (lane == 0) {
#pragma unroll
        for (int e = 0; e < NEXP; e++) red[wid][e] = acc[e];
    }
    __syncthreads();
    if (tid < 8) {
        float s = 0.f;
#pragma unroll
        for (int w = 0; w < 8; w++) s += red[w][tid];
        logits[tid] = s;
    }
    __syncthreads();
    if (tid == 0) {
        int best = 0; float bv = logits[0];
#pragma unroll
        for (int e = 1; e < NEXP; e++)
            if (logits[e] > bv) { bv = logits[e]; best = e; }
        int p = atomicAdd(&g_cnt[best], 1);
        g_list[best][p] = t;
    }
}

// ---------------------------------------------------------------------------
// Streaming weight convert: fp32 -> bf16 hi/lo, native layout (no transpose).
// blockIdx.z selects tensor {gate, up, down}. 8 floats per thread.
// ---------------------------------------------------------------------------
__global__ __launch_bounds__(256) void convert_w_kernel(
        const float* __restrict__ wg, const float* __restrict__ wu,
        const float* __restrict__ wd) {
    const float* src;
    __nv_bfloat16* dst;
    if (blockIdx.z == 0)      { src = wg; dst = g_Wg2; }
    else if (blockIdx.z == 1) { src = wu; dst = g_Wu2; }
    else                      { src = wd; dst = g_Wd2; }
    size_t i = ((size_t)blockIdx.x * 256 + threadIdx.x) * 8;
    float4 v0 = *(const float4*)(src + i);
    float4 v1 = *(const float4*)(src + i + 4);
    __nv_bfloat16 h[8], l[8];
    float f[8] = {v0.x, v0.y, v0.z, v0.w, v1.x, v1.y, v1.z, v1.w};
#pragma unroll
    for (int j = 0; j < 8; j++) {
        h[j] = __float2bfloat16(f[j]);
        l[j] = __float2bfloat16(f[j] - __bfloat162float(h[j]));
    }
    *(uint4*)(dst + i)       = *(uint4*)h;
    *(uint4*)(dst + WSZ + i) = *(uint4*)l;
}

// ---------------------------------------------------------------------------
// smem geometry (in halves)
// A: 128 rows x LDA=40 (hi @0, lo @5120)
// B: rows k (32) x LDB=72, matrices appended after A
// ---------------------------------------------------------------------------
#define LDA    40
#define LDB    72
#define OFF_AL 5120
#define OFF_B  10240
#define BMAT   (32 * LDB)            // 2304 halves per B half-matrix

// ffn1: B matrices: gh, gl, uh, ul
#define STG1   (OFF_B + 4 * BMAT)    // 19456 halves
#define SMEM1  (2 * STG1 * 2 + 512)
// ffn2: B matrices: dh, dl
#define STG2   (OFF_B + 2 * BMAT)    // 14848 halves
#define SMEM2  (2 * STG2 * 2 + 512)

// ---------------------------------------------------------------------------
// FFN1 fused: a = xWg, u = xWu, h = silu(a)*u -> bf16 hi/lo
// CTA 128 tok x 64 cols, 8 warps 32x32 (wm 4 x wn 2), K-chunk 32, 2-stage
// ---------------------------------------------------------------------------
__global__ __launch_bounds__(256, 2) void ffn1_kernel() {
    extern __shared__ __align__(16) __nv_bfloat16 sm[];
    const int e = blockIdx.z;
    const int cnt = g_cnt[e];
    const int row0 = blockIdx.x * 128;
    if (row0 >= cnt) return;
    const int col0 = blockIdx.y * 64;
    const int tid = threadIdx.x, lane = tid & 31, wid = tid >> 5;
    const int wm = (wid & 3) * 32, wn = (wid >> 2) * 32;

    int* toks = (int*)(sm + 2 * STG1);
    if (tid < 128) {
        int r = row0 + tid;
        toks[tid] = (r < cnt) ? g_list[e][r] : -1;
    }
    __syncthreads();
    const uint32_t sbase = smem_to_u32(sm);

    // ---- A cp.async source setup (rows = gathered tokens, k-contig) ----
    int r0i = tid >> 2,          s0 = tid & 3;
    int r1i = (tid + 256) >> 2,  s1 = (tid + 256) & 3;
    int t0 = toks[r0i], t1 = toks[r1i];
    const __nv_bfloat16* a0 = g_x2 + (size_t)(t0 < 0 ? 0 : t0) * DIM + s0 * 8;
    const __nv_bfloat16* a1 = g_x2 + (size_t)(t1 < 0 ? 0 : t1) * DIM + s1 * 8;
    uint32_t sz0 = (t0 >= 0) ? 16u : 0u;
    uint32_t sz1 = (t1 >= 0) ? 16u : 0u;
    uint32_t dA0 = (uint32_t)(r0i * LDA + s0 * 8) * 2;
    uint32_t dA1 = (uint32_t)(r1i * LDA + s1 * 8) * 2;

    // ---- B cp.async: native [d][h] rows; 32 k-rows x 64 cols per matrix ----
    // 4 half-matrices x 256 cp16 = 1024; thread does 4 (j = matrix index)
    int rbk = tid >> 3;          // 0..31 k-row
    int sbk = tid & 7;           // 0..7 col segment
    const __nv_bfloat16* wgp = g_Wg2 + (size_t)e * DIM * HID + (size_t)rbk * HID + col0 + sbk * 8;
    const __nv_bfloat16* wup = g_Wu2 + (size_t)e * DIM * HID + (size_t)rbk * HID + col0 + sbk * 8;
    uint32_t dB = (uint32_t)(OFF_B + rbk * LDB + sbk * 8) * 2;

    float accg[2][4][4], accu[2][4][4];
#pragma unroll
    for (int mt = 0; mt < 2; mt++)
#pragma unroll
        for (int nt = 0; nt < 4; nt++)
#pragma unroll
            for (int j = 0; j < 4; j++) { accg[mt][nt][j] = 0.f; accu[mt][nt][j] = 0.f; }

    const int NK = DIM / 32;   // 32

    {   // prologue chunk 0 -> stage 0
        uint32_t sb = sbase;
        cp16(sb + dA0, a0, sz0);
        cp16(sb + dA1, a1, sz1);
        cp16(sb + OFF_AL * 2 + dA0, a0 + XSZ, sz0);
        cp16(sb + OFF_AL * 2 + dA1, a1 + XSZ, sz1);
        cp16(sb + dB,                wgp, 16);
        cp16(sb + dB + BMAT * 2,     wgp + WSZ, 16);
        cp16(sb + dB + BMAT * 4,     wup, 16);
        cp16(sb + dB + BMAT * 6,     wup + WSZ, 16);
        CP_COMMIT();
    }

    // ldmatrix per-lane address components (halves -> bytes *2)
    const int lq = lane & 15, lh = lane >> 4;
    // A: row = wm + mt*16 + lq, col = ks + 8*lh
    uint32_t aAddr = sbase + (uint32_t)((wm + lq) * LDA + 8 * lh) * 2;
    // B: row(k) = ks + lq, col = n0 + 8*lh ; n0 = wn + nt2*16
    uint32_t bAddr = sbase + (uint32_t)(OFF_B + lq * LDB + wn + 8 * lh) * 2;

    for (int i = 0; i < NK; i++) {
        if (i + 1 < NK) {
            int ko = (i + 1) * 32;
            uint32_t sb = sbase + ((i + 1) & 1) * (STG1 * 2);
            cp16(sb + dA0, a0 + ko, sz0);
            cp16(sb + dA1, a1 + ko, sz1);
            cp16(sb + OFF_AL * 2 + dA0, a0 + XSZ + ko, sz0);
            cp16(sb + OFF_AL * 2 + dA1, a1 + XSZ + ko, sz1);
            const __nv_bfloat16* wg2 = wgp + (size_t)ko * HID;
            const __nv_bfloat16* wu2 = wup + (size_t)ko * HID;
            cp16(sb + dB,            wg2, 16);
            cp16(sb + dB + BMAT * 2, wg2 + WSZ, 16);
            cp16(sb + dB + BMAT * 4, wu2, 16);
            cp16(sb + dB + BMAT * 6, wu2 + WSZ, 16);
        }
        CP_COMMIT();
        CP_WAIT1();
        __syncthreads();

        uint32_t stg = (uint32_t)((i & 1) * (STG1 * 2));
#pragma unroll
        for (int ks = 0; ks < 32; ks += 16) {
            uint32_t ah[2][4], al[2][4];
#pragma unroll
            for (int mt = 0; mt < 2; mt++) {
                uint32_t ad = aAddr + stg + (uint32_t)(mt * 16 * LDA + ks) * 2;
                ldsm_x4(ah[mt], ad);
                ldsm_x4(al[mt], ad + OFF_AL * 2);
            }
            // gate
            {
                uint32_t bh[2][4], bl[2][4];
#pragma unroll
                for (int nt2 = 0; nt2 < 2; nt2++) {
                    uint32_t bd = bAddr + stg + (uint32_t)(ks * LDB + nt2 * 16) * 2;
                    ldsm_x4t(bh[nt2], bd);
                    ldsm_x4t(bl[nt2], bd + BMAT * 2);
                }
#pragma unroll
                for (int mt = 0; mt < 2; mt++)
#pragma unroll
                    for (int nt = 0; nt < 4; nt++) {
                        uint32_t* ph = &bh[nt >> 1][(nt & 1) * 2];
                        uint32_t* pl = &bl[nt >> 1][(nt & 1) * 2];
                        MMA_BF16(accg[mt][nt], ah[mt], ph[0], ph[1]);
                        MMA_BF16(accg[mt][nt], al[mt], ph[0], ph[1]);
                        MMA_BF16(accg[mt][nt], ah[mt], pl[0], pl[1]);
                    }
            }
            // up
            {
                uint32_t bh[2][4], bl[2][4];
#pragma unroll
                for (int nt2 = 0; nt2 < 2; nt2++) {
                    uint32_t bd = bAddr + stg + (uint32_t)(ks * LDB + nt2 * 16) * 2 + BMAT * 4;
                    ldsm_x4t(bh[nt2], bd);
                    ldsm_x4t(bl[nt2], bd + BMAT * 2);
                }
#pragma unroll
                for (int mt = 0; mt < 2; mt++)
#pragma unroll
                    for (int nt = 0; nt < 4; nt++) {
                        uint32_t* ph = &bh[nt >> 1][(nt & 1) * 2];
                        uint32_t* pl = &bl[nt >> 1][(nt & 1) * 2];
                        MMA_BF16(accu[mt][nt], ah[mt], ph[0], ph[1]);
                        MMA_BF16(accu[mt][nt], al[mt], ph[0], ph[1]);
                        MMA_BF16(accu[mt][nt], ah[mt], pl[0], pl[1]);
                    }
            }
        }
        __syncthreads();
    }

    // epilogue: h = silu(a)*u -> bf16 hi/lo scatter
    const int lr = lane >> 2, lk = (lane & 3) * 2;
#pragma unroll
    for (int mt = 0; mt < 2; mt++) {
        int ra = wm + mt * 16 + lr;
        int ta = toks[ra], tb = toks[ra + 8];
#pragma unroll
        for (int nt = 0; nt < 4; nt++) {
            int col = col0 + wn + nt * 8 + lk;
            if (ta >= 0) {
                float a0v = accg[mt][nt][0], a1v = accg[mt][nt][1];
                float u0v = accu[mt][nt][0], u1v = accu[mt][nt][1];
                float hv0 = a0v * u0v / (1.f + __expf(-a0v));
                float hv1 = a1v * u1v / (1.f + __expf(-a1v));
                __nv_bfloat16 hh0 = __float2bfloat16(hv0), hh1 = __float2bfloat16(hv1);
                __nv_bfloat16 hl0 = __float2bfloat16(hv0 - __bfloat162float(hh0));
                __nv_bfloat16 hl1 = __float2bfloat16(hv1 - __bfloat162float(hh1));
                size_t oo = (size_t)ta * HID + col;
                *(__nv_bfloat162*)(g_h2 + oo)       = __halves2bfloat162(hh0, hh1);
                *(__nv_bfloat162*)(g_h2 + HSZ + oo) = __halves2bfloat162(hl0, hl1);
            }
            if (tb >= 0) {
                float a0v = accg[mt][nt][2], a1v = accg[mt][nt][3];
                float u0v = accu[mt][nt][2], u1v = accu[mt][nt][3];
                float hv0 = a0v * u0v / (1.f + __expf(-a0v));
                float hv1 = a1v * u1v / (1.f + __expf(-a1v));
                __nv_bfloat16 hh0 = __float2bfloat16(hv0), hh1 = __float2bfloat16(hv1);
                __nv_bfloat16 hl0 = __float2bfloat16(hv0 - __bfloat162float(hh0));
                __nv_bfloat16 hl1 = __float2bfloat16(hv1 - __bfloat162float(hh1));
                size_t oo = (size_t)tb * HID + col;
                *(__nv_bfloat162*)(g_h2 + oo)       = __halves2bfloat162(hh0, hh1);
                *(__nv_bfloat162*)(g_h2 + HSZ + oo) = __halves2bfloat162(hl0, hl1);
            }
        }
    }
}

// ---------------------------------------------------------------------------
// FFN2: out = h Wd (fp32). CTA 128 x 64, K = HID, same skeleton
// ---------------------------------------------------------------------------
__global__ __launch_bounds__(256, 2) void ffn2_kernel(float* __restrict__ out) {
    extern __shared__ __align__(16) __nv_bfloat16 sm[];
    const int e = blockIdx.z;
    const int cnt = g_cnt[e];
    const int row0 = blockIdx.x * 128;
    if (row0 >= cnt) return;
    const int col0 = blockIdx.y * 64;
    const int tid = threadIdx.x, lane = tid & 31, wid = tid >> 5;
    const int wm = (wid & 3) * 32, wn = (wid >> 2) * 32;

    int* toks = (int*)(sm + 2 * STG2);
    if (tid < 128) {
        int r = row0 + tid;
        toks[tid] = (r < cnt) ? g_list[e][r] : -1;
    }
    __syncthreads();
    const uint32_t sbase = smem_to_u32(sm);

    int r0i = tid >> 2,          s0 = tid & 3;
    int r1i = (tid + 256) >> 2,  s1 = (tid + 256) & 3;
    int t0 = toks[r0i], t1 = toks[r1i];
    const __nv_bfloat16* a0 = g_h2 + (size_t)(t0 < 0 ? 0 : t0) * HID + s0 * 8;
    const __nv_bfloat16* a1 = g_h2 + (size_t)(t1 < 0 ? 0 : t1) * HID + s1 * 8;
    uint32_t sz0 = (t0 >= 0) ? 16u : 0u;
    uint32_t sz1 = (t1 >= 0) ? 16u : 0u;
    uint32_t dA0 = (uint32_t)(r0i * LDA + s0 * 8) * 2;
    uint32_t dA1 = (uint32_t)(r1i * LDA + s1 * 8) * 2;

    int rbk = tid >> 3, sbk = tid & 7;
    const __nv_bfloat16* wdp = g_Wd2 + (size_t)e * HID * DIM + (size_t)rbk * DIM + col0 + sbk * 8;
    uint32_t dB = (uint32_t)(OFF_B + rbk * LDB + sbk * 8) * 2;

    float acc[2][4][4];
#pragma unroll
    for (int mt = 0; mt < 2; mt++)
#pragma unroll
        for (int nt = 0; nt < 4; nt++)
#pragma unroll
            for (int j = 0; j < 4; j++) acc[mt][nt][j] = 0.f;

    const int NK = HID / 32;   // 64
    {
        uint32_t sb = sbase;
        cp16(sb + dA0, a0, sz0);
        cp16(sb + dA1, a1, sz1);
        cp16(sb + OFF_AL * 2 + dA0, a0 + HSZ, sz0);
        cp16(sb + OFF_AL * 2 + dA1, a1 + HSZ, sz1);
        cp16(sb + dB,            wdp, 16);
        cp16(sb + dB + BMAT * 2, wdp + WSZ, 16);
        CP_COMMIT();
    }

    const int lq = lane & 15, lh = lane >> 4;
    uint32_t aAddr = sbase + (uint32_t)((wm + lq) * LDA + 8 * lh) * 2;
    uint32_t bAddr = sbase + (uint32_t)(OFF_B + lq * LDB + wn + 8 * lh) * 2;

    for (int i = 0; i < NK; i++) {
        if (i + 1 < NK) {
            int ko = (i + 1) * 32;
            uint32_t sb = sbase + ((i + 1) & 1) * (STG2 * 2);
            cp16(sb + dA0, a0 + ko, sz0);
            cp16(sb + dA1, a1 + ko, sz1);
            cp16(sb + OFF_AL * 2 + dA0, a0 + HSZ + ko, sz0);
            cp16(sb + OFF_AL * 2 + dA1, a1 + HSZ + ko, sz1);
            const __nv_bfloat16* wd2 = wdp + (size_t)ko * DIM;
            cp16(sb + dB,            wd2, 16);
            cp16(sb + dB + BMAT * 2, wd2 + WSZ, 16);
        }
        CP_COMMIT();
        CP_WAIT1();
        __syncthreads();

        uint32_t stg = (uint32_t)((i & 1) * (STG2 * 2));
#pragma unroll
        for (int ks = 0; ks < 32; ks += 16) {
            uint32_t ah[2][4], al[2][4];
#pragma unroll
            for (int mt = 0; mt < 2; mt++) {
                uint32_t ad = aAddr + stg + (uint32_t)(mt * 16 * LDA + ks) * 2;
                ldsm_x4(ah[mt], ad);
                ldsm_x4(al[mt], ad + OFF_AL * 2);
            }
            uint32_t bh[2][4], bl[2][4];
#pragma unroll
            for (int nt2 = 0; nt2 < 2; nt2++) {
                uint32_t bd = bAddr + stg + (uint32_t)(ks * LDB + nt2 * 16) * 2;
                ldsm_x4t(bh[nt2], bd);
                ldsm_x4t(bl[nt2], bd + BMAT * 2);
            }
#pragma unroll
            for (int mt = 0; mt < 2; mt++)
#pragma unroll
                for (int nt = 0; nt < 4; nt++) {
                    uint32_t* ph = &bh[nt >> 1][(nt & 1) * 2];
                    uint32_t* pl = &bl[nt >> 1][(nt & 1) * 2];
                    MMA_BF16(acc[mt][nt], ah[mt], ph[0], ph[1]);
                    MMA_BF16(acc[mt][nt], al[mt], ph[0], ph[1]);
                    MMA_BF16(acc[mt][nt], ah[mt], pl[0], pl[1]);
                }
        }
        __syncthreads();
    }

    const int lr = lane >> 2, lk = (lane & 3) * 2;
#pragma unroll
    for (int mt = 0; mt < 2; mt++) {
        int ra = wm + mt * 16 + lr;
        int ta = toks[ra], tb = toks[ra + 8];
#pragma unroll
        for (int nt = 0; nt < 4; nt++) {
            int col = col0 + wn + nt * 8 + lk;
            if (ta >= 0)
                *(float2*)(out + (size_t)ta * DIM + col) =
                    make_float2(acc[mt][nt][0], acc[mt][nt][1]);
            if (tb >= 0)
                *(float2*)(out + (size_t)tb * DIM + col) =
                    make_float2(acc[mt][nt][2], acc[mt][nt][3]);
        }
    }
}

// ---------------------------------------------------------------------------
extern "C" void kernel_launch(void* const* d_in, const int* in_sizes, int n_in,
                              void* d_out, int out_size) {
    const float* x         = (const float*)d_in[0];
    const float* gate_w    = (const float*)d_in[1];
    const float* gate_bank = (const float*)d_in[2];
    const float* up_bank   = (const float*)d_in[3];
    const float* down_bank = (const float*)d_in[4];
    float* out = (float*)d_out;

    cudaFuncSetAttribute(ffn1_kernel,
                         cudaFuncAttributeMaxDynamicSharedMemorySize, SMEM1);
    cudaFuncSetAttribute(ffn2_kernel,
                         cudaFuncAttributeMaxDynamicSharedMemorySize, SMEM2);

    init_kernel<<<1, 32>>>();
    gate_convert_kernel<<<BT, 256>>>(x, gate_w);
    convert_w_kernel<<<dim3((unsigned)(WSZ / (256 * 8)), 1, 3), 256>>>(
        gate_bank, up_bank, down_bank);

    ffn1_kernel<<<dim3(BT / 128, HID / 64, NEXP), 256, SMEM1>>>();
    ffn2_kernel<<<dim3(BT / 128, DIM / 64, NEXP), 256, SMEM2>>>(out);
}

// round 7
// speedup vs baseline: 5.5128x; 2.0450x over previous
#include <cuda_runtime.h>
#include <cuda_fp16.h>
#include <cstdint>

#define BT   4096
#define DIM  1024
#define NEXP 8
#define HID  2048

#define XSZ  ((size_t)BT * DIM)
#define HSZ  ((size_t)BT * HID)
#define WSZ  ((size_t)NEXP * HID * DIM)

// ---------------------------------------------------------------------------
// Device global scratch (fp16 single precision-term everywhere)
// Weights in NATIVE orientation (gate/up: [E][D][H], down: [E][H][D]).
// ---------------------------------------------------------------------------
__device__ int g_cnt[NEXP];
__device__ int g_list[NEXP][BT];
__device__ __align__(16) __half g_x[XSZ];
__device__ __align__(16) __half g_h[HSZ];
__device__ __align__(16) __half g_Wg[WSZ];
__device__ __align__(16) __half g_Wu[WSZ];
__device__ __align__(16) __half g_Wd[WSZ];

// ---------------------------------------------------------------------------
// Helpers
// ---------------------------------------------------------------------------
__device__ __forceinline__ uint32_t smem_to_u32(const void* smem_ptr) {
    uint32_t addr;
    asm("{ .reg .u64 tmp; cvta.to.shared.u64 tmp, %1; cvt.u32.u64 %0, tmp; }"
        : "=r"(addr) : "l"(smem_ptr));
    return addr;
}

__device__ __forceinline__ void cp16(uint32_t dst, const void* src, uint32_t sz) {
    asm volatile("cp.async.cg.shared.global [%0], [%1], 16, %2;\n"
                 :: "r"(dst), "l"(src), "r"(sz));
}
#define CP_COMMIT() asm volatile("cp.async.commit_group;\n" ::: "memory")
#define CP_WAIT2()  asm volatile("cp.async.wait_group 2;\n" ::: "memory")

__device__ __forceinline__ void ldsm_x4(uint32_t* r, uint32_t addr) {
    asm volatile("ldmatrix.sync.aligned.m8n8.x4.shared.b16 {%0,%1,%2,%3}, [%4];"
        : "=r"(r[0]), "=r"(r[1]), "=r"(r[2]), "=r"(r[3]) : "r"(addr));
}
__device__ __forceinline__ void ldsm_x4t(uint32_t* r, uint32_t addr) {
    asm volatile("ldmatrix.sync.aligned.m8n8.x4.trans.shared.b16 {%0,%1,%2,%3}, [%4];"
        : "=r"(r[0]), "=r"(r[1]), "=r"(r[2]), "=r"(r[3]) : "r"(addr));
}

#define MMA_F16(acc, a, b0, b1) \
    asm volatile("mma.sync.aligned.m16n8k16.row.col.f32.f16.f16.f32 " \
        "{%0,%1,%2,%3}, {%4,%5,%6,%7}, {%8,%9}, {%0,%1,%2,%3};" \
        : "+f"((acc)[0]), "+f"((acc)[1]), "+f"((acc)[2]), "+f"((acc)[3]) \
        : "r"((a)[0]), "r"((a)[1]), "r"((a)[2]), "r"((a)[3]), \
          "r"(b0), "r"(b1))

// ---------------------------------------------------------------------------
__global__ void init_kernel() {
    if (threadIdx.x < NEXP) g_cnt[threadIdx.x] = 0;
}

// ---------------------------------------------------------------------------
// Fused x convert (fp16) + gating + scatter. One token/block.
// ---------------------------------------------------------------------------
__global__ __launch_bounds__(256) void gate_convert_kernel(
        const float* __restrict__ x, const float* __restrict__ gw) {
    __shared__ float red[8][8];
    __shared__ float logits[8];
    const int t = blockIdx.x;
    const int tid = threadIdx.x;
    const int lane = tid & 31, wid = tid >> 5;

    float4 v = ((const float4*)x)[(size_t)t * (DIM / 4) + tid];

    __half2 p0 = __halves2half2(__float2half_rn(v.x), __float2half_rn(v.y));
    __half2 p1 = __halves2half2(__float2half_rn(v.z), __float2half_rn(v.w));
    size_t o = (size_t)t * DIM + tid * 4;
    *(__half2*)(g_x + o)     = p0;
    *(__half2*)(g_x + o + 2) = p1;

    float acc[NEXP];
#pragma unroll
    for (int e = 0; e < NEXP; e++) {
        float4 g = ((const float4*)(gw + (size_t)e * DIM))[tid];
        acc[e] = v.x * g.x + v.y * g.y + v.z * g.z + v.w * g.w;
    }
#pragma unroll
    for (int e = 0; e < NEXP; e++) {
#pragma unroll
        for (int off = 16; off > 0; off >>= 1)
            acc[e] += __shfl_xor_sync(0xffffffffu, acc[e], off);
    }
    if (lane == 0) {
#pragma unroll
        for (int e = 0; e < NEXP; e++) red[wid][e] = acc[e];
    }
    __syncthreads();
    if (tid < 8) {
        float s = 0.f;
#pragma unroll
        for (int w = 0; w < 8; w++) s += red[w][tid];
        logits[tid] = s;
    }
    __syncthreads();
    if (tid == 0) {
        int best = 0; float bv = logits[0];
#pragma unroll
        for (int e = 1; e < NEXP; e++)
            if (logits[e] > bv) { bv = logits[e]; best = e; }
        int p = atomicAdd(&g_cnt[best], 1);
        g_list[best][p] = t;
    }
}

// ---------------------------------------------------------------------------
// Streaming weight convert: fp32 -> fp16, native layout.
// ---------------------------------------------------------------------------
__global__ __launch_bounds__(256) void convert_w_kernel(
        const float* __restrict__ wg, const float* __restrict__ wu,
        const float* __restrict__ wd) {
    const float* src;
    __half* dst;
    if (blockIdx.z == 0)      { src = wg; dst = g_Wg; }
    else if (blockIdx.z == 1) { src = wu; dst = g_Wu; }
    else                      { src = wd; dst = g_Wd; }
    size_t i = ((size_t)blockIdx.x * 256 + threadIdx.x) * 8;
    float4 v0 = *(const float4*)(src + i);
    float4 v1 = *(const float4*)(src + i + 4);
    __half h[8];
    h[0] = __float2half_rn(v0.x); h[1] = __float2half_rn(v0.y);
    h[2] = __float2half_rn(v0.z); h[3] = __float2half_rn(v0.w);
    h[4] = __float2half_rn(v1.x); h[5] = __float2half_rn(v1.y);
    h[6] = __float2half_rn(v1.z); h[7] = __float2half_rn(v1.w);
    *(uint4*)(dst + i) = *(uint4*)h;
}

// ---------------------------------------------------------------------------
// smem geometry (halves)
// A: 128 x LDA=40 @0 (5120 h). B: 32 k-rows x LDB=72 per matrix.
// ffn1: Bg @5120, Bu @7424 -> stage 9728 h. ffn2: Bd @5120 -> stage 7424 h.
// 3-stage pipeline.
// ---------------------------------------------------------------------------
#define LDA    40
#define LDB    72
#define OFF_B  5120
#define BMAT   (32 * LDB)             // 2304 halves
#define STG1   (OFF_B + 2 * BMAT)     // 9728
#define STG2   (OFF_B + 1 * BMAT)     // 7424
#define SMEM1  (3 * STG1 * 2 + 512)
#define SMEM2  (3 * STG2 * 2 + 512)

// ---------------------------------------------------------------------------
// FFN1: a = xWg, u = xWu, h = silu(a)*u -> fp16
// CTA 128 tok x 64 cols, 8 warps 32x32 (wm 4 x wn 2), K-chunk 32
// ---------------------------------------------------------------------------
__global__ __launch_bounds__(256, 2) void ffn1_kernel() {
    extern __shared__ __align__(16) __half sm[];
    const int e = blockIdx.z;
    const int cnt = g_cnt[e];
    const int row0 = blockIdx.x * 128;
    if (row0 >= cnt) return;
    const int col0 = blockIdx.y * 64;
    const int tid = threadIdx.x, lane = tid & 31, wid = tid >> 5;
    const int wm = (wid & 3) * 32, wn = (wid >> 2) * 32;

    int* toks = (int*)(sm + 3 * STG1);
    if (tid < 128) {
        int r = row0 + tid;
        toks[tid] = (r < cnt) ? g_list[e][r] : -1;
    }
    __syncthreads();
    const uint32_t sbase = smem_to_u32(sm);

    // A: chunk = 128 rows x 32 halves = 512 cp16; 2 per thread
    int r0i = tid >> 2,          s0 = tid & 3;
    int r1i = (tid + 256) >> 2,  s1 = (tid + 256) & 3;
    int t0 = toks[r0i], t1 = toks[r1i];
    const __half* a0 = g_x + (size_t)(t0 < 0 ? 0 : t0) * DIM + s0 * 8;
    const __half* a1 = g_x + (size_t)(t1 < 0 ? 0 : t1) * DIM + s1 * 8;
    uint32_t sz0 = (t0 >= 0) ? 16u : 0u;
    uint32_t sz1 = (t1 >= 0) ? 16u : 0u;
    uint32_t dA0 = (uint32_t)(r0i * LDA + s0 * 8) * 2;
    uint32_t dA1 = (uint32_t)(r1i * LDA + s1 * 8) * 2;
    // B: each matrix 32x64 = 256 cp16; 1 per thread per matrix
    int rbk = tid >> 3, sbk = tid & 7;
    const __half* wgp = g_Wg + (size_t)e * DIM * HID + (size_t)rbk * HID + col0 + sbk * 8;
    const __half* wup = g_Wu + (size_t)e * DIM * HID + (size_t)rbk * HID + col0 + sbk * 8;
    uint32_t dB = (uint32_t)(OFF_B + rbk * LDB + sbk * 8) * 2;

    float accg[2][4][4], accu[2][4][4];
#pragma unroll
    for (int mt = 0; mt < 2; mt++)
#pragma unroll
        for (int nt = 0; nt < 4; nt++)
#pragma unroll
            for (int j = 0; j < 4; j++) { accg[mt][nt][j] = 0.f; accu[mt][nt][j] = 0.f; }

    const int NK = DIM / 32;   // 32

    // prologue: issue chunks 0 and 1
#pragma unroll
    for (int pc = 0; pc < 2; pc++) {
        int ko = pc * 32;
        uint32_t sb = sbase + (uint32_t)(pc * STG1 * 2);
        cp16(sb + dA0, a0 + ko, sz0);
        cp16(sb + dA1, a1 + ko, sz1);
        cp16(sb + dB,            wgp + (size_t)ko * HID, 16);
        cp16(sb + dB + BMAT * 2, wup + (size_t)ko * HID, 16);
        CP_COMMIT();
    }

    const int lq = lane & 15, lh = lane >> 4;
    uint32_t aAddr = sbase + (uint32_t)((wm + lq) * LDA + 8 * lh) * 2;
    uint32_t bAddr = sbase + (uint32_t)(OFF_B + lq * LDB + wn + 8 * lh) * 2;

    int stage = 0;
    for (int i = 0; i < NK; i++) {
        if (i + 2 < NK) {
            int ko = (i + 2) * 32;
            int ps = (stage + 2) % 3;
            uint32_t sb = sbase + (uint32_t)(ps * STG1 * 2);
            cp16(sb + dA0, a0 + ko, sz0);
            cp16(sb + dA1, a1 + ko, sz1);
            cp16(sb + dB,            wgp + (size_t)ko * HID, 16);
            cp16(sb + dB + BMAT * 2, wup + (size_t)ko * HID, 16);
        }
        CP_COMMIT();
        CP_WAIT2();
        __syncthreads();

        uint32_t stg = (uint32_t)(stage * STG1 * 2);
#pragma unroll
        for (int ks = 0; ks < 32; ks += 16) {
            uint32_t a_[2][4];
#pragma unroll
            for (int mt = 0; mt < 2; mt++)
                ldsm_x4(a_[mt], aAddr + stg + (uint32_t)(mt * 16 * LDA + ks) * 2);
            uint32_t bg[2][4], bu[2][4];
#pragma unroll
            for (int nt2 = 0; nt2 < 2; nt2++) {
                uint32_t bd = bAddr + stg + (uint32_t)(ks * LDB + nt2 * 16) * 2;
                ldsm_x4t(bg[nt2], bd);
                ldsm_x4t(bu[nt2], bd + BMAT * 2);
            }
#pragma unroll
            for (int mt = 0; mt < 2; mt++)
#pragma unroll
                for (int nt = 0; nt < 4; nt++) {
                    uint32_t* pg = &bg[nt >> 1][(nt & 1) * 2];
                    uint32_t* pu = &bu[nt >> 1][(nt & 1) * 2];
                    MMA_F16(accg[mt][nt], a_[mt], pg[0], pg[1]);
                    MMA_F16(accu[mt][nt], a_[mt], pu[0], pu[1]);
                }
        }
        __syncthreads();
        stage = (stage + 1) % 3;
    }

    // epilogue: h = silu(a)*u -> fp16 scatter
    const int lr = lane >> 2, lk = (lane & 3) * 2;
#pragma unroll
    for (int mt = 0; mt < 2; mt++) {
        int ra = wm + mt * 16 + lr;
        int ta = toks[ra], tb = toks[ra + 8];
#pragma unroll
        for (int nt = 0; nt < 4; nt++) {
            int col = col0 + wn + nt * 8 + lk;
            if (ta >= 0) {
                float a0v = accg[mt][nt][0], a1v = accg[mt][nt][1];
                float u0v = accu[mt][nt][0], u1v = accu[mt][nt][1];
                float hv0 = a0v * u0v / (1.f + __expf(-a0v));
                float hv1 = a1v * u1v / (1.f + __expf(-a1v));
                *(__half2*)(g_h + (size_t)ta * HID + col) =
                    __halves2half2(__float2half_rn(hv0), __float2half_rn(hv1));
            }
            if (tb >= 0) {
                float a0v = accg[mt][nt][2], a1v = accg[mt][nt][3];
                float u0v = accu[mt][nt][2], u1v = accu[mt][nt][3];
                float hv0 = a0v * u0v / (1.f + __expf(-a0v));
                float hv1 = a1v * u1v / (1.f + __expf(-a1v));
                *(__half2*)(g_h + (size_t)tb * HID + col) =
                    __halves2half2(__float2half_rn(hv0), __float2half_rn(hv1));
            }
        }
    }
}

// ---------------------------------------------------------------------------
// FFN2: out = h Wd (fp32). CTA 128 x 64, K = HID
// ---------------------------------------------------------------------------
__global__ __launch_bounds__(256, 3) void ffn2_kernel(float* __restrict__ out) {
    extern __shared__ __align__(16) __half sm[];
    const int e = blockIdx.z;
    const int cnt = g_cnt[e];
    const int row0 = blockIdx.x * 128;
    if (row0 >= cnt) return;
    const int col0 = blockIdx.y * 64;
    const int tid = threadIdx.x, lane = tid & 31, wid = tid >> 5;
    const int wm = (wid & 3) * 32, wn = (wid >> 2) * 32;

    int* toks = (int*)(sm + 3 * STG2);
    if (tid < 128) {
        int r = row0 + tid;
        toks[tid] = (r < cnt) ? g_list[e][r] : -1;
    }
    __syncthreads();
    const uint32_t sbase = smem_to_u32(sm);

    int r0i = tid >> 2,          s0 = tid & 3;
    int r1i = (tid + 256) >> 2,  s1 = (tid + 256) & 3;
    int t0 = toks[r0i], t1 = toks[r1i];
    const __half* a0 = g_h + (size_t)(t0 < 0 ? 0 : t0) * HID + s0 * 8;
    const __half* a1 = g_h + (size_t)(t1 < 0 ? 0 : t1) * HID + s1 * 8;
    uint32_t sz0 = (t0 >= 0) ? 16u : 0u;
    uint32_t sz1 = (t1 >= 0) ? 16u : 0u;
    uint32_t dA0 = (uint32_t)(r0i * LDA + s0 * 8) * 2;
    uint32_t dA1 = (uint32_t)(r1i * LDA + s1 * 8) * 2;
    int rbk = tid >> 3, sbk = tid & 7;
    const __half* wdp = g_Wd + (size_t)e * HID * DIM + (size_t)rbk * DIM + col0 + sbk * 8;
    uint32_t dB = (uint32_t)(OFF_B + rbk * LDB + sbk * 8) * 2;

    float acc[2][4][4];
#pragma unroll
    for (int mt = 0; mt < 2; mt++)
#pragma unroll
        for (int nt = 0; nt < 4; nt++)
#pragma unroll
            for (int j = 0; j < 4; j++) acc[mt][nt][j] = 0.f;

    const int NK = HID / 32;   // 64

#pragma unroll
    for (int pc = 0; pc < 2; pc++) {
        int ko = pc * 32;
        uint32_t sb = sbase + (uint32_t)(pc * STG2 * 2);
        cp16(sb + dA0, a0 + ko, sz0);
        cp16(sb + dA1, a1 + ko, sz1);
        cp16(sb + dB, wdp + (size_t)ko * DIM, 16);
        CP_COMMIT();
    }

    const int lq = lane & 15, lh = lane >> 4;
    uint32_t aAddr = sbase + (uint32_t)((wm + lq) * LDA + 8 * lh) * 2;
    uint32_t bAddr = sbase + (uint32_t)(OFF_B + lq * LDB + wn + 8 * lh) * 2;

    int stage = 0;
    for (int i = 0; i < NK; i++) {
        if (i + 2 < NK) {
            int ko = (i + 2) * 32;
            int ps = (stage + 2) % 3;
            uint32_t sb = sbase + (uint32_t)(ps * STG2 * 2);
            cp16(sb + dA0, a0 + ko, sz0);
            cp16(sb + dA1, a1 + ko, sz1);
            cp16(sb + dB, wdp + (size_t)ko * DIM, 16);
        }
        CP_COMMIT();
        CP_WAIT2();
        __syncthreads();

        uint32_t stg = (uint32_t)(stage * STG2 * 2);
#pragma unroll
        for (int ks = 0; ks < 32; ks += 16) {
            uint32_t a_[2][4];
#pragma unroll
            for (int mt = 0; mt < 2; mt++)
                ldsm_x4(a_[mt], aAddr + stg + (uint32_t)(mt * 16 * LDA + ks) * 2);
            uint32_t bd_[2][4];
#pragma unroll
            for (int nt2 = 0; nt2 < 2; nt2++)
                ldsm_x4t(bd_[nt2], bAddr + stg + (uint32_t)(ks * LDB + nt2 * 16) * 2);
#pragma unroll
            for (int mt = 0; mt < 2; mt++)
#pragma unroll
                for (int nt = 0; nt < 4; nt++) {
                    uint32_t* pb = &bd_[nt >> 1][(nt & 1) * 2];
                    MMA_F16(acc[mt][nt], a_[mt], pb[0], pb[1]);
                }
        }
        __syncthreads();
        stage = (stage + 1) % 3;
    }

    const int lr = lane >> 2, lk = (lane & 3) * 2;
#pragma unroll
    for (int mt = 0; mt < 2; mt++) {
        int ra = wm + mt * 16 + lr;
        int ta = toks[ra], tb = toks[ra + 8];
#pragma unroll
        for (int nt = 0; nt < 4; nt++) {
            int col = col0 + wn + nt * 8 + lk;
            if (ta >= 0)
                *(float2*)(out + (size_t)ta * DIM + col) =
                    make_float2(acc[mt][nt][0], acc[mt][nt][1]);
            if (tb >= 0)
                *(float2*)(out + (size_t)tb * DIM + col) =
                    make_float2(acc[mt][nt][2], acc[mt][nt][3]);
        }
    }
}

// ---------------------------------------------------------------------------
extern "C" void kernel_launch(void* const* d_in, const int* in_sizes, int n_in,
                              void* d_out, int out_size) {
    const float* x         = (const float*)d_in[0];
    const float* gate_w    = (const float*)d_in[1];
    const float* gate_bank = (const float*)d_in[2];
    const float* up_bank   = (const float*)d_in[3];
    const float* down_bank = (const float*)d_in[4];
    float* out = (float*)d_out;

    cudaFuncSetAttribute(ffn1_kernel,
                         cudaFuncAttributeMaxDynamicSharedMemorySize, SMEM1);
    cudaFuncSetAttribute(ffn2_kernel,
                         cudaFuncAttributeMaxDynamicSharedMemorySize, SMEM2);

    init_kernel<<<1, 32>>>();
    gate_convert_kernel<<<BT, 256>>>(x, gate_w);
    convert_w_kernel<<<dim3((unsigned)(WSZ / (256 * 8)), 1, 3), 256>>>(
        gate_bank, up_bank, down_bank);

    ffn1_kernel<<<dim3(BT / 128, HID / 64, NEXP), 256, SMEM1>>>();
    ffn2_kernel<<<dim3(BT / 128, DIM / 64, NEXP), 256, SMEM2>>>(out);
}

// round 8
// speedup vs baseline: 6.0057x; 1.0894x over previous
#include <cuda_runtime.h>
#include <cuda_fp16.h>
#include <cstdint>

#define BT   4096
#define DIM  1024
#define NEXP 8
#define HID  2048

#define XSZ  ((size_t)BT * DIM)
#define HSZ  ((size_t)BT * HID)
#define WSZ  ((size_t)NEXP * HID * DIM)

// ---------------------------------------------------------------------------
__device__ int g_cnt[NEXP];
__device__ int g_list[NEXP][BT];
__device__ __align__(16) __half g_x[XSZ];
__device__ __align__(16) __half g_h[HSZ];
__device__ __align__(16) __half g_Wg[WSZ];
__device__ __align__(16) __half g_Wu[WSZ];
__device__ __align__(16) __half g_Wd[WSZ];

// ---------------------------------------------------------------------------
__device__ __forceinline__ uint32_t smem_to_u32(const void* smem_ptr) {
    uint32_t addr;
    asm("{ .reg .u64 tmp; cvta.to.shared.u64 tmp, %1; cvt.u32.u64 %0, tmp; }"
        : "=r"(addr) : "l"(smem_ptr));
    return addr;
}

__device__ __forceinline__ void cp16(uint32_t dst, const void* src, uint32_t sz) {
    asm volatile("cp.async.cg.shared.global [%0], [%1], 16, %2;\n"
                 :: "r"(dst), "l"(src), "r"(sz));
}
#define CP_COMMIT() asm volatile("cp.async.commit_group;\n" ::: "memory")
#define CP_WAIT2()  asm volatile("cp.async.wait_group 2;\n" ::: "memory")

__device__ __forceinline__ void ldsm_x4(uint32_t* r, uint32_t addr) {
    asm volatile("ldmatrix.sync.aligned.m8n8.x4.shared.b16 {%0,%1,%2,%3}, [%4];"
        : "=r"(r[0]), "=r"(r[1]), "=r"(r[2]), "=r"(r[3]) : "r"(addr));
}
__device__ __forceinline__ void ldsm_x4t(uint32_t* r, uint32_t addr) {
    asm volatile("ldmatrix.sync.aligned.m8n8.x4.trans.shared.b16 {%0,%1,%2,%3}, [%4];"
        : "=r"(r[0]), "=r"(r[1]), "=r"(r[2]), "=r"(r[3]) : "r"(addr));
}

#define MMA_F16(acc, a, b0, b1) \
    asm volatile("mma.sync.aligned.m16n8k16.row.col.f32.f16.f16.f32 " \
        "{%0,%1,%2,%3}, {%4,%5,%6,%7}, {%8,%9}, {%0,%1,%2,%3};" \
        : "+f"((acc)[0]), "+f"((acc)[1]), "+f"((acc)[2]), "+f"((acc)[3]) \
        : "r"((a)[0]), "r"((a)[1]), "r"((a)[2]), "r"((a)[3]), \
          "r"(b0), "r"(b1))

// ---------------------------------------------------------------------------
__global__ void init_kernel() {
    if (threadIdx.x < NEXP) g_cnt[threadIdx.x] = 0;
}

// ---------------------------------------------------------------------------
// Fused x convert (fp16) + gating + scatter. One token/block.
// ---------------------------------------------------------------------------
__global__ __launch_bounds__(256) void gate_convert_kernel(
        const float* __restrict__ x, const float* __restrict__ gw) {
    __shared__ float red[8][8];
    __shared__ float logits[8];
    const int t = blockIdx.x;
    const int tid = threadIdx.x;
    const int lane = tid & 31, wid = tid >> 5;

    float4 v = ((const float4*)x)[(size_t)t * (DIM / 4) + tid];

    __half2 p0 = __halves2half2(__float2half_rn(v.x), __float2half_rn(v.y));
    __half2 p1 = __halves2half2(__float2half_rn(v.z), __float2half_rn(v.w));
    size_t o = (size_t)t * DIM + tid * 4;
    *(__half2*)(g_x + o)     = p0;
    *(__half2*)(g_x + o + 2) = p1;

    float acc[NEXP];
#pragma unroll
    for (int e = 0; e < NEXP; e++) {
        float4 g = ((const float4*)(gw + (size_t)e * DIM))[tid];
        acc[e] = v.x * g.x + v.y * g.y + v.z * g.z + v.w * g.w;
    }
#pragma unroll
    for (int e = 0; e < NEXP; e++) {
#pragma unroll
        for (int off = 16; off > 0; off >>= 1)
            acc[e] += __shfl_xor_sync(0xffffffffu, acc[e], off);
    }
    if (lane == 0) {
#pragma unroll
        for (int e = 0; e < NEXP; e++) red[wid][e] = acc[e];
    }
    __syncthreads();
    if (tid < 8) {
        float s = 0.f;
#pragma unroll
        for (int w = 0; w < 8; w++) s += red[w][tid];
        logits[tid] = s;
    }
    __syncthreads();
    if (tid == 0) {
        int best = 0; float bv = logits[0];
#pragma unroll
        for (int e = 1; e < NEXP; e++)
            if (logits[e] > bv) { bv = logits[e]; best = e; }
        int p = atomicAdd(&g_cnt[best], 1);
        g_list[best][p] = t;
    }
}

// ---------------------------------------------------------------------------
__global__ __launch_bounds__(256) void convert_w_kernel(
        const float* __restrict__ wg, const float* __restrict__ wu,
        const float* __restrict__ wd) {
    const float* src;
    __half* dst;
    if (blockIdx.z == 0)      { src = wg; dst = g_Wg; }
    else if (blockIdx.z == 1) { src = wu; dst = g_Wu; }
    else                      { src = wd; dst = g_Wd; }
    size_t i = ((size_t)blockIdx.x * 256 + threadIdx.x) * 8;
    float4 v0 = *(const float4*)(src + i);
    float4 v1 = *(const float4*)(src + i + 4);
    __half h[8];
    h[0] = __float2half_rn(v0.x); h[1] = __float2half_rn(v0.y);
    h[2] = __float2half_rn(v0.z); h[3] = __float2half_rn(v0.w);
    h[4] = __float2half_rn(v1.x); h[5] = __float2half_rn(v1.y);
    h[6] = __float2half_rn(v1.z); h[7] = __float2half_rn(v1.w);
    *(uint4*)(dst + i) = *(uint4*)h;
}

// ---------------------------------------------------------------------------
// smem geometry (halves). K-chunk = 64.
// ffn1: A 128 x LDA=72 @0 (9216), Bg 64x72 @9216, Bu @13824; stage 18432 h
// ffn2: A 128 x 72 @0 (9216), Bd 64x LDB2=136 @9216; stage 17920 h
// 3-stage pipelines.
// ---------------------------------------------------------------------------
#define KC     64
#define LDA    72
#define LDB    72
#define LDB2   136
#define OFF_B  9216
#define BMAT   (64 * LDB)              // 4608 halves
#define STG1   (OFF_B + 2 * BMAT)      // 18432
#define STG2   (OFF_B + 64 * LDB2)     // 17920
#define SMEM1  (3 * STG1 * 2 + 512)
#define SMEM2  (3 * STG2 * 2 + 512)

// ---------------------------------------------------------------------------
// FFN1: a = xWg, u = xWu, h = silu(a)*u -> fp16
// CTA 128 tok x 64 cols, 8 warps 32x32 (wm 4 x wn 2), K-chunk 64
// ---------------------------------------------------------------------------
__global__ __launch_bounds__(256, 2) void ffn1_kernel() {
    extern __shared__ __align__(16) __half sm[];
    const int e = blockIdx.z;
    const int cnt = g_cnt[e];
    const int row0 = blockIdx.x * 128;
    if (row0 >= cnt) return;
    const int col0 = blockIdx.y * 64;
    const int tid = threadIdx.x, lane = tid & 31, wid = tid >> 5;
    const int wm = (wid & 3) * 32, wn = (wid >> 2) * 32;

    int* toks = (int*)(sm + 3 * STG1);
    if (tid < 128) {
        int r = row0 + tid;
        toks[tid] = (r < cnt) ? g_list[e][r] : -1;
    }
    __syncthreads();
    const uint32_t sbase = smem_to_u32(sm);

    // A: chunk 128 rows x 64 halves = 1024 cp16; 4 per thread
    const __half* aP[4];
    uint32_t szA[4], dA[4];
#pragma unroll
    for (int j = 0; j < 4; j++) {
        int idx = tid + j * 256;
        int r = idx >> 3, s = idx & 7;
        int t = toks[r];
        aP[j] = g_x + (size_t)(t < 0 ? 0 : t) * DIM + s * 8;
        szA[j] = (t >= 0) ? 16u : 0u;
        dA[j] = (uint32_t)(r * LDA + s * 8) * 2;
    }
    // B: each matrix 64x64 = 512 cp16; 2 per thread per matrix
    const __half *wgP[2], *wuP[2];
    uint32_t dB[2];
#pragma unroll
    for (int j = 0; j < 2; j++) {
        int idx = tid + j * 256;
        int rb = idx >> 3, sb_ = idx & 7;
        wgP[j] = g_Wg + (size_t)e * DIM * HID + (size_t)rb * HID + col0 + sb_ * 8;
        wuP[j] = g_Wu + (size_t)e * DIM * HID + (size_t)rb * HID + col0 + sb_ * 8;
        dB[j] = (uint32_t)(OFF_B + rb * LDB + sb_ * 8) * 2;
    }

    float accg[2][4][4], accu[2][4][4];
#pragma unroll
    for (int mt = 0; mt < 2; mt++)
#pragma unroll
        for (int nt = 0; nt < 4; nt++)
#pragma unroll
            for (int j = 0; j < 4; j++) { accg[mt][nt][j] = 0.f; accu[mt][nt][j] = 0.f; }

    const int NK = DIM / KC;   // 16

#pragma unroll
    for (int pc = 0; pc < 2; pc++) {
        int ko = pc * KC;
        uint32_t sb = sbase + (uint32_t)(pc * STG1 * 2);
#pragma unroll
        for (int j = 0; j < 4; j++) cp16(sb + dA[j], aP[j] + ko, szA[j]);
#pragma unroll
        for (int j = 0; j < 2; j++) {
            cp16(sb + dB[j],            wgP[j] + (size_t)ko * HID, 16);
            cp16(sb + dB[j] + BMAT * 2, wuP[j] + (size_t)ko * HID, 16);
        }
        CP_COMMIT();
    }

    const int lq = lane & 15, lh = lane >> 4;
    uint32_t aAddr = sbase + (uint32_t)((wm + lq) * LDA + 8 * lh) * 2;
    uint32_t bAddr = sbase + (uint32_t)(OFF_B + lq * LDB + wn + 8 * lh) * 2;

    int stage = 0;
    for (int i = 0; i < NK; i++) {
        if (i + 2 < NK) {
            int ko = (i + 2) * KC;
            int ps = stage + 2; if (ps >= 3) ps -= 3;
            uint32_t sb = sbase + (uint32_t)(ps * STG1 * 2);
#pragma unroll
            for (int j = 0; j < 4; j++) cp16(sb + dA[j], aP[j] + ko, szA[j]);
#pragma unroll
            for (int j = 0; j < 2; j++) {
                cp16(sb + dB[j],            wgP[j] + (size_t)ko * HID, 16);
                cp16(sb + dB[j] + BMAT * 2, wuP[j] + (size_t)ko * HID, 16);
            }
        }
        CP_COMMIT();
        CP_WAIT2();
        __syncthreads();

        uint32_t stg = (uint32_t)(stage * STG1 * 2);
#pragma unroll
        for (int ks = 0; ks < KC; ks += 16) {
            uint32_t a_[2][4];
#pragma unroll
            for (int mt = 0; mt < 2; mt++)
                ldsm_x4(a_[mt], aAddr + stg + (uint32_t)(mt * 16 * LDA + ks) * 2);
            uint32_t bg[2][4], bu[2][4];
#pragma unroll
            for (int nt2 = 0; nt2 < 2; nt2++) {
                uint32_t bd = bAddr + stg + (uint32_t)(ks * LDB + nt2 * 16) * 2;
                ldsm_x4t(bg[nt2], bd);
                ldsm_x4t(bu[nt2], bd + BMAT * 2);
            }
#pragma unroll
            for (int mt = 0; mt < 2; mt++)
#pragma unroll
                for (int nt = 0; nt < 4; nt++) {
                    uint32_t* pg = &bg[nt >> 1][(nt & 1) * 2];
                    uint32_t* pu = &bu[nt >> 1][(nt & 1) * 2];
                    MMA_F16(accg[mt][nt], a_[mt], pg[0], pg[1]);
                    MMA_F16(accu[mt][nt], a_[mt], pu[0], pu[1]);
                }
        }
        __syncthreads();
        stage++; if (stage >= 3) stage = 0;
    }

    const int lr = lane >> 2, lk = (lane & 3) * 2;
#pragma unroll
    for (int mt = 0; mt < 2; mt++) {
        int ra = wm + mt * 16 + lr;
        int ta = toks[ra], tb = toks[ra + 8];
#pragma unroll
        for (int nt = 0; nt < 4; nt++) {
            int col = col0 + wn + nt * 8 + lk;
            if (ta >= 0) {
                float a0v = accg[mt][nt][0], a1v = accg[mt][nt][1];
                float u0v = accu[mt][nt][0], u1v = accu[mt][nt][1];
                float hv0 = a0v * u0v / (1.f + __expf(-a0v));
                float hv1 = a1v * u1v / (1.f + __expf(-a1v));
                *(__half2*)(g_h + (size_t)ta * HID + col) =
                    __halves2half2(__float2half_rn(hv0), __float2half_rn(hv1));
            }
            if (tb >= 0) {
                float a0v = accg[mt][nt][2], a1v = accg[mt][nt][3];
                float u0v = accu[mt][nt][2], u1v = accu[mt][nt][3];
                float hv0 = a0v * u0v / (1.f + __expf(-a0v));
                float hv1 = a1v * u1v / (1.f + __expf(-a1v));
                *(__half2*)(g_h + (size_t)tb * HID + col) =
                    __halves2half2(__float2half_rn(hv0), __float2half_rn(hv1));
            }
        }
    }
}

// ---------------------------------------------------------------------------
// FFN2: out = h Wd (fp32). CTA 128 x 128, 8 warps 32x64 (wm 4 x wn 2), K-chunk 64
// ---------------------------------------------------------------------------
__global__ __launch_bounds__(256, 2) void ffn2_kernel(float* __restrict__ out) {
    extern __shared__ __align__(16) __half sm[];
    const int e = blockIdx.z;
    const int cnt = g_cnt[e];
    const int row0 = blockIdx.x * 128;
    if (row0 >= cnt) return;
    const int col0 = blockIdx.y * 128;
    const int tid = threadIdx.x, lane = tid & 31, wid = tid >> 5;
    const int wm = (wid & 3) * 32, wn = (wid >> 2) * 64;

    int* toks = (int*)(sm + 3 * STG2);
    if (tid < 128) {
        int r = row0 + tid;
        toks[tid] = (r < cnt) ? g_list[e][r] : -1;
    }
    __syncthreads();
    const uint32_t sbase = smem_to_u32(sm);

    const __half* aP[4];
    uint32_t szA[4], dA[4];
#pragma unroll
    for (int j = 0; j < 4; j++) {
        int idx = tid + j * 256;
        int r = idx >> 3, s = idx & 7;
        int t = toks[r];
        aP[j] = g_h + (size_t)(t < 0 ? 0 : t) * HID + s * 8;
        szA[j] = (t >= 0) ? 16u : 0u;
        dA[j] = (uint32_t)(r * LDA + s * 8) * 2;
    }
    // B: 64 k-rows x 128 cols = 1024 cp16; 4 per thread
    const __half* wdP[4];
    uint32_t dB[4];
#pragma unroll
    for (int j = 0; j < 4; j++) {
        int idx = tid + j * 256;
        int rb = idx >> 4, sb_ = idx & 15;
        wdP[j] = g_Wd + (size_t)e * HID * DIM + (size_t)rb * DIM + col0 + sb_ * 8;
        dB[j] = (uint32_t)(OFF_B + rb * LDB2 + sb_ * 8) * 2;
    }

    float acc[2][8][4];
#pragma unroll
    for (int mt = 0; mt < 2; mt++)
#pragma unroll
        for (int nt = 0; nt < 8; nt++)
#pragma unroll
            for (int j = 0; j < 4; j++) acc[mt][nt][j] = 0.f;

    const int NK = HID / KC;   // 32

#pragma unroll
    for (int pc = 0; pc < 2; pc++) {
        int ko = pc * KC;
        uint32_t sb = sbase + (uint32_t)(pc * STG2 * 2);
#pragma unroll
        for (int j = 0; j < 4; j++) cp16(sb + dA[j], aP[j] + ko, szA[j]);
#pragma unroll
        for (int j = 0; j < 4; j++) cp16(sb + dB[j], wdP[j] + (size_t)ko * DIM, 16);
        CP_COMMIT();
    }

    const int lq = lane & 15, lh = lane >> 4;
    uint32_t aAddr = sbase + (uint32_t)((wm + lq) * LDA + 8 * lh) * 2;
    uint32_t bAddr = sbase + (uint32_t)(OFF_B + lq * LDB2 + wn + 8 * lh) * 2;

    int stage = 0;
    for (int i = 0; i < NK; i++) {
        if (i + 2 < NK) {
            int ko = (i + 2) * KC;
            int ps = stage + 2; if (ps >= 3) ps -= 3;
            uint32_t sb = sbase + (uint32_t)(ps * STG2 * 2);
#pragma unroll
            for (int j = 0; j < 4; j++) cp16(sb + dA[j], aP[j] + ko, szA[j]);
#pragma unroll
            for (int j = 0; j < 4; j++) cp16(sb + dB[j], wdP[j] + (size_t)ko * DIM, 16);
        }
        CP_COMMIT();
        CP_WAIT2();
        __syncthreads();

        uint32_t stg = (uint32_t)(stage * STG2 * 2);
#pragma unroll
        for (int ks = 0; ks < KC; ks += 16) {
            uint32_t a_[2][4];
#pragma unroll
            for (int mt = 0; mt < 2; mt++)
                ldsm_x4(a_[mt], aAddr + stg + (uint32_t)(mt * 16 * LDA + ks) * 2);
            uint32_t bd_[4][4];
#pragma unroll
            for (int nt2 = 0; nt2 < 4; nt2++)
                ldsm_x4t(bd_[nt2], bAddr + stg + (uint32_t)(ks * LDB2 + nt2 * 16) * 2);
#pragma unroll
            for (int mt = 0; mt < 2; mt++)
#pragma unroll
                for (int nt = 0; nt < 8; nt++) {
                    uint32_t* pb = &bd_[nt >> 1][(nt & 1) * 2];
                    MMA_F16(acc[mt][nt], a_[mt], pb[0], pb[1]);
                }
        }
        __syncthreads();
        stage++; if (stage >= 3) stage = 0;
    }

    const int lr = lane >> 2, lk = (lane & 3) * 2;
#pragma unroll
    for (int mt = 0; mt < 2; mt++) {
        int ra = wm + mt * 16 + lr;
        int ta = toks[ra], tb = toks[ra + 8];
#pragma unroll
        for (int nt = 0; nt < 8; nt++) {
            int col = col0 + wn + nt * 8 + lk;
            if (ta >= 0)
                *(float2*)(out + (size_t)ta * DIM + col) =
                    make_float2(acc[mt][nt][0], acc[mt][nt][1]);
            if (tb >= 0)
                *(float2*)(out + (size_t)tb * DIM + col) =
                    make_float2(acc[mt][nt][2], acc[mt][nt][3]);
        }
    }
}

// ---------------------------------------------------------------------------
extern "C" void kernel_launch(void* const* d_in, const int* in_sizes, int n_in,
                              void* d_out, int out_size) {
    const float* x         = (const float*)d_in[0];
    const float* gate_w    = (const float*)d_in[1];
    const float* gate_bank = (const float*)d_in[2];
    const float* up_bank   = (const float*)d_in[3];
    const float* down_bank = (const float*)d_in[4];
    float* out = (float*)d_out;

    cudaFuncSetAttribute(ffn1_kernel,
                         cudaFuncAttributeMaxDynamicSharedMemorySize, SMEM1);
    cudaFuncSetAttribute(ffn2_kernel,
                         cudaFuncAttributeMaxDynamicSharedMemorySize, SMEM2);

    init_kernel<<<1, 32>>>();
    gate_convert_kernel<<<BT, 256>>>(x, gate_w);
    convert_w_kernel<<<dim3((unsigned)(WSZ / (256 * 8)), 1, 3), 256>>>(
        gate_bank, up_bank, down_bank);

    ffn1_kernel<<<dim3(BT / 128, HID / 64, NEXP), 256, SMEM1>>>();
    ffn2_kernel<<<dim3(BT / 128, DIM / 128, NEXP), 256, SMEM2>>>(out);
}

// round 9
// speedup vs baseline: 6.0541x; 1.0081x over previous
#include <cuda_runtime.h>
#include <cuda_fp16.h>
#include <cstdint>

#define BT   4096
#define DIM  1024
#define NEXP 8
#define HID  2048

#define XSZ  ((size_t)BT * DIM)
#define HSZ  ((size_t)BT * HID)
#define WSZ  ((size_t)NEXP * HID * DIM)

// ---------------------------------------------------------------------------
__device__ int g_cnt[NEXP];
__device__ int g_list[NEXP][BT];
__device__ __align__(16) __half g_x[XSZ];
__device__ __align__(16) __half g_h[HSZ];
__device__ __align__(16) __half g_Wg[WSZ];
__device__ __align__(16) __half g_Wu[WSZ];
__device__ __align__(16) __half g_Wd[WSZ];

// ---------------------------------------------------------------------------
__device__ __forceinline__ uint32_t smem_to_u32(const void* smem_ptr) {
    uint32_t addr;
    asm("{ .reg .u64 tmp; cvta.to.shared.u64 tmp, %1; cvt.u32.u64 %0, tmp; }"
        : "=r"(addr) : "l"(smem_ptr));
    return addr;
}

__device__ __forceinline__ void cp16(uint32_t dst, const void* src, uint32_t sz) {
    asm volatile("cp.async.cg.shared.global [%0], [%1], 16, %2;\n"
                 :: "r"(dst), "l"(src), "r"(sz));
}
#define CP_COMMIT() asm volatile("cp.async.commit_group;\n" ::: "memory")
#define CP_WAIT1()  asm volatile("cp.async.wait_group 1;\n" ::: "memory")

__device__ __forceinline__ void ldsm_x4(uint32_t* r, uint32_t addr) {
    asm volatile("ldmatrix.sync.aligned.m8n8.x4.shared.b16 {%0,%1,%2,%3}, [%4];"
        : "=r"(r[0]), "=r"(r[1]), "=r"(r[2]), "=r"(r[3]) : "r"(addr));
}
__device__ __forceinline__ void ldsm_x4t(uint32_t* r, uint32_t addr) {
    asm volatile("ldmatrix.sync.aligned.m8n8.x4.trans.shared.b16 {%0,%1,%2,%3}, [%4];"
        : "=r"(r[0]), "=r"(r[1]), "=r"(r[2]), "=r"(r[3]) : "r"(addr));
}

#define MMA_F16(acc, a, b0, b1) \
    asm volatile("mma.sync.aligned.m16n8k16.row.col.f32.f16.f16.f32 " \
        "{%0,%1,%2,%3}, {%4,%5,%6,%7}, {%8,%9}, {%0,%1,%2,%3};" \
        : "+f"((acc)[0]), "+f"((acc)[1]), "+f"((acc)[2]), "+f"((acc)[3]) \
        : "r"((a)[0]), "r"((a)[1]), "r"((a)[2]), "r"((a)[3]), \
          "r"(b0), "r"(b1))

// ---------------------------------------------------------------------------
__global__ void init_kernel() {
    if (threadIdx.x < NEXP) g_cnt[threadIdx.x] = 0;
}

// ---------------------------------------------------------------------------
// Fused x convert (fp16) + gating + scatter. One token/block.
// ---------------------------------------------------------------------------
__global__ __launch_bounds__(256) void gate_convert_kernel(
        const float* __restrict__ x, const float* __restrict__ gw) {
    __shared__ float red[8][8];
    __shared__ float logits[8];
    const int t = blockIdx.x;
    const int tid = threadIdx.x;
    const int lane = tid & 31, wid = tid >> 5;

    float4 v = ((const float4*)x)[(size_t)t * (DIM / 4) + tid];

    __half2 p0 = __halves2half2(__float2half_rn(v.x), __float2half_rn(v.y));
    __half2 p1 = __halves2half2(__float2half_rn(v.z), __float2half_rn(v.w));
    size_t o = (size_t)t * DIM + tid * 4;
    *(__half2*)(g_x + o)     = p0;
    *(__half2*)(g_x + o + 2) = p1;

    float acc[NEXP];
#pragma unroll
    for (int e = 0; e < NEXP; e++) {
        float4 g = ((const float4*)(gw + (size_t)e * DIM))[tid];
        acc[e] = v.x * g.x + v.y * g.y + v.z * g.z + v.w * g.w;
    }
#pragma unroll
    for (int e = 0; e < NEXP; e++) {
#pragma unroll
        for (int off = 16; off > 0; off >>= 1)
            acc[e] += __shfl_xor_sync(0xffffffffu, acc[e], off);
    }
    if (lane == 0) {
#pragma unroll
        for (int e = 0; e < NEXP; e++) red[wid][e] = acc[e];
    }
    __syncthreads();
    if (tid < 8) {
        float s = 0.f;
#pragma unroll
        for (int w = 0; w < 8; w++) s += red[w][tid];
        logits[tid] = s;
    }
    __syncthreads();
    if (tid == 0) {
        int best = 0; float bv = logits[0];
#pragma unroll
        for (int e = 1; e < NEXP; e++)
            if (logits[e] > bv) { bv = logits[e]; best = e; }
        int p = atomicAdd(&g_cnt[best], 1);
        g_list[best][p] = t;
    }
}

// ---------------------------------------------------------------------------
__global__ __launch_bounds__(256) void convert_w_kernel(
        const float* __restrict__ wg, const float* __restrict__ wu,
        const float* __restrict__ wd) {
    const float* src;
    __half* dst;
    if (blockIdx.z == 0)      { src = wg; dst = g_Wg; }
    else if (blockIdx.z == 1) { src = wu; dst = g_Wu; }
    else                      { src = wd; dst = g_Wd; }
    size_t i = ((size_t)blockIdx.x * 256 + threadIdx.x) * 8;
    float4 v0 = *(const float4*)(src + i);
    float4 v1 = *(const float4*)(src + i + 4);
    __half h[8];
    h[0] = __float2half_rn(v0.x); h[1] = __float2half_rn(v0.y);
    h[2] = __float2half_rn(v0.z); h[3] = __float2half_rn(v0.w);
    h[4] = __float2half_rn(v1.x); h[5] = __float2half_rn(v1.y);
    h[6] = __float2half_rn(v1.z); h[7] = __float2half_rn(v1.w);
    *(uint4*)(dst + i) = *(uint4*)h;
}

// ---------------------------------------------------------------------------
// smem geometry (halves). K-chunk = 64, 3 stages.
// ffn1: A 128 x LDA=72 @0 (9216), Bg 64x72 @9216, Bu @13824; stage 18432 h
// ffn2: A 128 x 72 @0 (9216), Bd 64 x LDB2=136 @9216; stage 17920 h
// ---------------------------------------------------------------------------
#define KC     64
#define LDA    72
#define LDB    72
#define LDB2   136
#define OFF_B  9216
#define BMAT   (64 * LDB)              // 4608 halves
#define STG1   (OFF_B + 2 * BMAT)      // 18432
#define STG2   (OFF_B + 64 * LDB2)     // 17920
#define SMEM1  (3 * STG1 * 2 + 512)
#define SMEM2  (3 * STG2 * 2 + 512)

// ---------------------------------------------------------------------------
// FFN1: a = xWg, u = xWu, h = silu(a)*u -> fp16
// CTA 128 tok x 64 cols, 8 warps 32x32 (wm 4 x wn 2), K-chunk 64
// Single __syncthreads per mainloop iteration (load-after-sync, 3 stages).
// ---------------------------------------------------------------------------
__global__ __launch_bounds__(256, 2) void ffn1_kernel() {
    extern __shared__ __align__(16) __half sm[];
    const int e = blockIdx.z;
    const int cnt = g_cnt[e];
    const int row0 = blockIdx.x * 128;
    if (row0 >= cnt) return;
    const int col0 = blockIdx.y * 64;
    const int tid = threadIdx.x, lane = tid & 31, wid = tid >> 5;
    const int wm = (wid & 3) * 32, wn = (wid >> 2) * 32;

    int* toks = (int*)(sm + 3 * STG1);
    if (tid < 128) {
        int r = row0 + tid;
        toks[tid] = (r < cnt) ? g_list[e][r] : -1;
    }
    __syncthreads();
    const uint32_t sbase = smem_to_u32(sm);

    // A: chunk 128 rows x 64 halves = 1024 cp16; 4 per thread
    const __half* aP[4];
    uint32_t szA[4], dA[4];
#pragma unroll
    for (int j = 0; j < 4; j++) {
        int idx = tid + j * 256;
        int r = idx >> 3, s = idx & 7;
        int t = toks[r];
        aP[j] = g_x + (size_t)(t < 0 ? 0 : t) * DIM + s * 8;
        szA[j] = (t >= 0) ? 16u : 0u;
        dA[j] = (uint32_t)(r * LDA + s * 8) * 2;
    }
    // B: each matrix 64x64 = 512 cp16; 2 per thread per matrix
    const __half *wgP[2], *wuP[2];
    uint32_t dB[2];
#pragma unroll
    for (int j = 0; j < 2; j++) {
        int idx = tid + j * 256;
        int rb = idx >> 3, sb_ = idx & 7;
        wgP[j] = g_Wg + (size_t)e * DIM * HID + (size_t)rb * HID + col0 + sb_ * 8;
        wuP[j] = g_Wu + (size_t)e * DIM * HID + (size_t)rb * HID + col0 + sb_ * 8;
        dB[j] = (uint32_t)(OFF_B + rb * LDB + sb_ * 8) * 2;
    }

    float accg[2][4][4], accu[2][4][4];
#pragma unroll
    for (int mt = 0; mt < 2; mt++)
#pragma unroll
        for (int nt = 0; nt < 4; nt++)
#pragma unroll
            for (int j = 0; j < 4; j++) { accg[mt][nt][j] = 0.f; accu[mt][nt][j] = 0.f; }

    const int NK = DIM / KC;   // 16

    // prologue: issue chunks 0 and 1 (one commit group each)
#pragma unroll
    for (int pc = 0; pc < 2; pc++) {
        int ko = pc * KC;
        uint32_t sb = sbase + (uint32_t)(pc * STG1 * 2);
#pragma unroll
        for (int j = 0; j < 4; j++) cp16(sb + dA[j], aP[j] + ko, szA[j]);
#pragma unroll
        for (int j = 0; j < 2; j++) {
            cp16(sb + dB[j],            wgP[j] + (size_t)ko * HID, 16);
            cp16(sb + dB[j] + BMAT * 2, wuP[j] + (size_t)ko * HID, 16);
        }
        CP_COMMIT();
    }

    const int lq = lane & 15, lh = lane >> 4;
    uint32_t aAddr = sbase + (uint32_t)((wm + lq) * LDA + 8 * lh) * 2;
    uint32_t bAddr = sbase + (uint32_t)(OFF_B + lq * LDB + wn + 8 * lh) * 2;

    int stage = 0;
    for (int i = 0; i < NK; i++) {
        // chunk i complete (≤1 group pending), and all warps done with the
        // stage we are about to overwrite (computed at i-1, barrier below).
        CP_WAIT1();
        __syncthreads();

        // issue chunk i+2 into stage (stage+2)%3 — nobody reads it now
        if (i + 2 < NK) {
            int ko = (i + 2) * KC;
            int ps = stage + 2; if (ps >= 3) ps -= 3;
            uint32_t sb = sbase + (uint32_t)(ps * STG1 * 2);
#pragma unroll
            for (int j = 0; j < 4; j++) cp16(sb + dA[j], aP[j] + ko, szA[j]);
#pragma unroll
            for (int j = 0; j < 2; j++) {
                cp16(sb + dB[j],            wgP[j] + (size_t)ko * HID, 16);
                cp16(sb + dB[j] + BMAT * 2, wuP[j] + (size_t)ko * HID, 16);
            }
        }
        CP_COMMIT();

        uint32_t stg = (uint32_t)(stage * STG1 * 2);
#pragma unroll
        for (int ks = 0; ks < KC; ks += 16) {
            uint32_t a_[2][4];
#pragma unroll
            for (int mt = 0; mt < 2; mt++)
                ldsm_x4(a_[mt], aAddr + stg + (uint32_t)(mt * 16 * LDA + ks) * 2);
            uint32_t bg[2][4], bu[2][4];
#pragma unroll
            for (int nt2 = 0; nt2 < 2; nt2++) {
                uint32_t bd = bAddr + stg + (uint32_t)(ks * LDB + nt2 * 16) * 2;
                ldsm_x4t(bg[nt2], bd);
                ldsm_x4t(bu[nt2], bd + BMAT * 2);
            }
#pragma unroll
            for (int mt = 0; mt < 2; mt++)
#pragma unroll
                for (int nt = 0; nt < 4; nt++) {
                    uint32_t* pg = &bg[nt >> 1][(nt & 1) * 2];
                    uint32_t* pu = &bu[nt >> 1][(nt & 1) * 2];
                    MMA_F16(accg[mt][nt], a_[mt], pg[0], pg[1]);
                    MMA_F16(accu[mt][nt], a_[mt], pu[0], pu[1]);
                }
        }
        stage++; if (stage >= 3) stage = 0;
    }

    const int lr = lane >> 2, lk = (lane & 3) * 2;
#pragma unroll
    for (int mt = 0; mt < 2; mt++) {
        int ra = wm + mt * 16 + lr;
        int ta = toks[ra], tb = toks[ra + 8];
#pragma unroll
        for (int nt = 0; nt < 4; nt++) {
            int col = col0 + wn + nt * 8 + lk;
            if (ta >= 0) {
                float a0v = accg[mt][nt][0], a1v = accg[mt][nt][1];
                float u0v = accu[mt][nt][0], u1v = accu[mt][nt][1];
                float hv0 = a0v * u0v / (1.f + __expf(-a0v));
                float hv1 = a1v * u1v / (1.f + __expf(-a1v));
                *(__half2*)(g_h + (size_t)ta * HID + col) =
                    __halves2half2(__float2half_rn(hv0), __float2half_rn(hv1));
            }
            if (tb >= 0) {
                float a0v = accg[mt][nt][2], a1v = accg[mt][nt][3];
                float u0v = accu[mt][nt][2], u1v = accu[mt][nt][3];
                float hv0 = a0v * u0v / (1.f + __expf(-a0v));
                float hv1 = a1v * u1v / (1.f + __expf(-a1v));
                *(__half2*)(g_h + (size_t)tb * HID + col) =
                    __halves2half2(__float2half_rn(hv0), __float2half_rn(hv1));
            }
        }
    }
}

// ---------------------------------------------------------------------------
// FFN2: out = h Wd (fp32). CTA 128 x 128, 8 warps 32x64 (wm 4 x wn 2), K-chunk 64
// ---------------------------------------------------------------------------
__global__ __launch_bounds__(256, 2) void ffn2_kernel(float* __restrict__ out) {
    extern __shared__ __align__(16) __half sm[];
    const int e = blockIdx.z;
    const int cnt = g_cnt[e];
    const int row0 = blockIdx.x * 128;
    if (row0 >= cnt) return;
    const int col0 = blockIdx.y * 128;
    const int tid = threadIdx.x, lane = tid & 31, wid = tid >> 5;
    const int wm = (wid & 3) * 32, wn = (wid >> 2) * 64;

    int* toks = (int*)(sm + 3 * STG2);
    if (tid < 128) {
        int r = row0 + tid;
        toks[tid] = (r < cnt) ? g_list[e][r] : -1;
    }
    __syncthreads();
    const uint32_t sbase = smem_to_u32(sm);

    const __half* aP[4];
    uint32_t szA[4], dA[4];
#pragma unroll
    for (int j = 0; j < 4; j++) {
        int idx = tid + j * 256;
        int r = idx >> 3, s = idx & 7;
        int t = toks[r];
        aP[j] = g_h + (size_t)(t < 0 ? 0 : t) * HID + s * 8;
        szA[j] = (t >= 0) ? 16u : 0u;
        dA[j] = (uint32_t)(r * LDA + s * 8) * 2;
    }
    const __half* wdP[4];
    uint32_t dB[4];
#pragma unroll
    for (int j = 0; j < 4; j++) {
        int idx = tid + j * 256;
        int rb = idx >> 4, sb_ = idx & 15;
        wdP[j] = g_Wd + (size_t)e * HID * DIM + (size_t)rb * DIM + col0 + sb_ * 8;
        dB[j] = (uint32_t)(OFF_B + rb * LDB2 + sb_ * 8) * 2;
    }

    float acc[2][8][4];
#pragma unroll
    for (int mt = 0; mt < 2; mt++)
#pragma unroll
        for (int nt = 0; nt < 8; nt++)
#pragma unroll
            for (int j = 0; j < 4; j++) acc[mt][nt][j] = 0.f;

    const int NK = HID / KC;   // 32

#pragma unroll
    for (int pc = 0; pc < 2; pc++) {
        int ko = pc * KC;
        uint32_t sb = sbase + (uint32_t)(pc * STG2 * 2);
#pragma unroll
        for (int j = 0; j < 4; j++) cp16(sb + dA[j], aP[j] + ko, szA[j]);
#pragma unroll
        for (int j = 0; j < 4; j++) cp16(sb + dB[j], wdP[j] + (size_t)ko * DIM, 16);
        CP_COMMIT();
    }

    const int lq = lane & 15, lh = lane >> 4;
    uint32_t aAddr = sbase + (uint32_t)((wm + lq) * LDA + 8 * lh) * 2;
    uint32_t bAddr = sbase + (uint32_t)(OFF_B + lq * LDB2 + wn + 8 * lh) * 2;

    int stage = 0;
    for (int i = 0; i < NK; i++) {
        CP_WAIT1();
        __syncthreads();

        if (i + 2 < NK) {
            int ko = (i + 2) * KC;
            int ps = stage + 2; if (ps >= 3) ps -= 3;
            uint32_t sb = sbase + (uint32_t)(ps * STG2 * 2);
#pragma unroll
            for (int j = 0; j < 4; j++) cp16(sb + dA[j], aP[j] + ko, szA[j]);
#pragma unroll
            for (int j = 0; j < 4; j++) cp16(sb + dB[j], wdP[j] + (size_t)ko * DIM, 16);
        }
        CP_COMMIT();

        uint32_t stg = (uint32_t)(stage * STG2 * 2);
#pragma unroll
        for (int ks = 0; ks < KC; ks += 16) {
            uint32_t a_[2][4];
#pragma unroll
            for (int mt = 0; mt < 2; mt++)
                ldsm_x4(a_[mt], aAddr + stg + (uint32_t)(mt * 16 * LDA + ks) * 2);
            uint32_t bd_[4][4];
#pragma unroll
            for (int nt2 = 0; nt2 < 4; nt2++)
                ldsm_x4t(bd_[nt2], bAddr + stg + (uint32_t)(ks * LDB2 + nt2 * 16) * 2);
#pragma unroll
            for (int mt = 0; mt < 2; mt++)
#pragma unroll
                for (int nt = 0; nt < 8; nt++) {
                    uint32_t* pb = &bd_[nt >> 1][(nt & 1) * 2];
                    MMA_F16(acc[mt][nt], a_[mt], pb[0], pb[1]);
                }
        }
        stage++; if (stage >= 3) stage = 0;
    }

    const int lr = lane >> 2, lk = (lane & 3) * 2;
#pragma unroll
    for (int mt = 0; mt < 2; mt++) {
        int ra = wm + mt * 16 + lr;
        int ta = toks[ra], tb = toks[ra + 8];
#pragma unroll
        for (int nt = 0; nt < 8; nt++) {
            int col = col0 + wn + nt * 8 + lk;
            if (ta >= 0)
                *(float2*)(out + (size_t)ta * DIM + col) =
                    make_float2(acc[mt][nt][0], acc[mt][nt][1]);
            if (tb >= 0)
                *(float2*)(out + (size_t)tb * DIM + col) =
                    make_float2(acc[mt][nt][2], acc[mt][nt][3]);
        }
    }
}

// ---------------------------------------------------------------------------
extern "C" void kernel_launch(void* const* d_in, const int* in_sizes, int n_in,
                              void* d_out, int out_size) {
    const float* x         = (const float*)d_in[0];
    const float* gate_w    = (const float*)d_in[1];
    const float* gate_bank = (const float*)d_in[2];
    const float* up_bank   = (const float*)d_in[3];
    const float* down_bank = (const float*)d_in[4];
    float* out = (float*)d_out;

    cudaFuncSetAttribute(ffn1_kernel,
                         cudaFuncAttributeMaxDynamicSharedMemorySize, SMEM1);
    cudaFuncSetAttribute(ffn2_kernel,
                         cudaFuncAttributeMaxDynamicSharedMemorySize, SMEM2);

    init_kernel<<<1, 32>>>();
    gate_convert_kernel<<<BT, 256>>>(x, gate_w);
    convert_w_kernel<<<dim3((unsigned)(WSZ / (256 * 8)), 1, 3), 256>>>(
        gate_bank, up_bank, down_bank);

    ffn1_kernel<<<dim3(BT / 128, HID / 64, NEXP), 256, SMEM1>>>();
    ffn2_kernel<<<dim3(BT / 128, DIM / 128, NEXP), 256, SMEM2>>>(out);
}

// round 10
// speedup vs baseline: 6.0696x; 1.0026x over previous
#include <cuda_runtime.h>
#include <cuda_fp16.h>
#include <cstdint>

#define BT   4096
#define DIM  1024
#define NEXP 8
#define HID  2048

#define XSZ  ((size_t)BT * DIM)
#define HSZ  ((size_t)BT * HID)
#define WSZ  ((size_t)NEXP * HID * DIM)

// ---------------------------------------------------------------------------
__device__ int g_cnt[NEXP];
__device__ int g_list[NEXP][BT];
__device__ __align__(16) __half g_x[XSZ];
__device__ __align__(16) __half g_h[HSZ];
__device__ __align__(16) __half g_Wg[WSZ];
__device__ __align__(16) __half g_Wu[WSZ];
__device__ __align__(16) __half g_Wd[WSZ];

// ---------------------------------------------------------------------------
__device__ __forceinline__ uint32_t smem_to_u32(const void* smem_ptr) {
    uint32_t addr;
    asm("{ .reg .u64 tmp; cvta.to.shared.u64 tmp, %1; cvt.u32.u64 %0, tmp; }"
        : "=r"(addr) : "l"(smem_ptr));
    return addr;
}

__device__ __forceinline__ void cp16(uint32_t dst, const void* src, uint32_t sz) {
    asm volatile("cp.async.cg.shared.global [%0], [%1], 16, %2;\n"
                 :: "r"(dst), "l"(src), "r"(sz));
}
#define CP_COMMIT() asm volatile("cp.async.commit_group;\n" ::: "memory")
#define CP_WAIT1()  asm volatile("cp.async.wait_group 1;\n" ::: "memory")

__device__ __forceinline__ void ldsm_x4(uint32_t* r, uint32_t addr) {
    asm volatile("ldmatrix.sync.aligned.m8n8.x4.shared.b16 {%0,%1,%2,%3}, [%4];"
        : "=r"(r[0]), "=r"(r[1]), "=r"(r[2]), "=r"(r[3]) : "r"(addr));
}
__device__ __forceinline__ void ldsm_x4t(uint32_t* r, uint32_t addr) {
    asm volatile("ldmatrix.sync.aligned.m8n8.x4.trans.shared.b16 {%0,%1,%2,%3}, [%4];"
        : "=r"(r[0]), "=r"(r[1]), "=r"(r[2]), "=r"(r[3]) : "r"(addr));
}

#define MMA_F16(acc, a, b0, b1) \
    asm volatile("mma.sync.aligned.m16n8k16.row.col.f32.f16.f16.f32 " \
        "{%0,%1,%2,%3}, {%4,%5,%6,%7}, {%8,%9}, {%0,%1,%2,%3};" \
        : "+f"((acc)[0]), "+f"((acc)[1]), "+f"((acc)[2]), "+f"((acc)[3]) \
        : "r"((a)[0]), "r"((a)[1]), "r"((a)[2]), "r"((a)[3]), \
          "r"(b0), "r"(b1))

// convert 8 consecutive floats -> 8 halves (one uint4 store)
__device__ __forceinline__ void cvt8(const float* __restrict__ s,
                                     __half* __restrict__ d) {
    float4 v0 = *(const float4*)s;
    float4 v1 = *(const float4*)(s + 4);
    __half h[8];
    h[0] = __float2half_rn(v0.x); h[1] = __float2half_rn(v0.y);
    h[2] = __float2half_rn(v0.z); h[3] = __float2half_rn(v0.w);
    h[4] = __float2half_rn(v1.x); h[5] = __float2half_rn(v1.y);
    h[6] = __float2half_rn(v1.z); h[7] = __float2half_rn(v1.w);
    *(uint4*)d = *(uint4*)h;
}

// ---------------------------------------------------------------------------
__global__ void init_kernel() {
    if (threadIdx.x < NEXP) g_cnt[threadIdx.x] = 0;
}

// ---------------------------------------------------------------------------
// Fused: x convert (fp16) + gating + scatter + Wg/Wu fp32->fp16 conversion.
// One token/block (4096 blocks); each block also converts a 4096-float slice
// of Wg and of Wu (16 floats per thread each).
// ---------------------------------------------------------------------------
__global__ __launch_bounds__(256) void gate_convert_kernel(
        const float* __restrict__ x, const float* __restrict__ gw,
        const float* __restrict__ wg_src, const float* __restrict__ wu_src) {
    __shared__ float red[8][8];
    __shared__ float logits[8];
    const int t = blockIdx.x;
    const int tid = threadIdx.x;
    const int lane = tid & 31, wid = tid >> 5;

    float4 v = ((const float4*)x)[(size_t)t * (DIM / 4) + tid];

    __half2 p0 = __halves2half2(__float2half_rn(v.x), __float2half_rn(v.y));
    __half2 p1 = __halves2half2(__float2half_rn(v.z), __float2half_rn(v.w));
    size_t o = (size_t)t * DIM + tid * 4;
    *(__half2*)(g_x + o)     = p0;
    *(__half2*)(g_x + o + 2) = p1;

    float acc[NEXP];
#pragma unroll
    for (int e = 0; e < NEXP; e++) {
        float4 g = ((const float4*)(gw + (size_t)e * DIM))[tid];
        acc[e] = v.x * g.x + v.y * g.y + v.z * g.z + v.w * g.w;
    }
#pragma unroll
    for (int e = 0; e < NEXP; e++) {
#pragma unroll
        for (int off = 16; off > 0; off >>= 1)
            acc[e] += __shfl_xor_sync(0xffffffffu, acc[e], off);
    }
    if (lane == 0) {
#pragma unroll
        for (int e = 0; e < NEXP; e++) red[wid][e] = acc[e];
    }
    __syncthreads();
    if (tid < 8) {
        float s = 0.f;
#pragma unroll
        for (int w = 0; w < 8; w++) s += red[w][tid];
        logits[tid] = s;
    }
    __syncthreads();
    if (tid == 0) {
        int best = 0; float bv = logits[0];
#pragma unroll
        for (int e = 1; e < NEXP; e++)
            if (logits[e] > bv) { bv = logits[e]; best = e; }
        int p = atomicAdd(&g_cnt[best], 1);
        g_list[best][p] = t;
    }

    // Convert Wg/Wu slices: 4096 floats per matrix per block = 16/thread.
    {
        size_t base = (size_t)t * 4096 + (size_t)tid * 16;
        cvt8(wg_src + base,     g_Wg + base);
        cvt8(wg_src + base + 8, g_Wg + base + 8);
        cvt8(wu_src + base,     g_Wu + base);
        cvt8(wu_src + base + 8, g_Wu + base + 8);
    }
}

// ---------------------------------------------------------------------------
// smem geometry (halves). K-chunk = 64, 3 stages.
// ffn1: A 128 x LDA=72 @0 (9216), Bg 64x72 @9216, Bu @13824; stage 18432 h
// ffn2: A 128 x 72 @0 (9216), Bd 64 x LDB2=136 @9216; stage 17920 h
// ---------------------------------------------------------------------------
#define KC     64
#define LDA    72
#define LDB    72
#define LDB2   136
#define OFF_B  9216
#define BMAT   (64 * LDB)              // 4608 halves
#define STG1   (OFF_B + 2 * BMAT)      // 18432
#define STG2   (OFF_B + 64 * LDB2)     // 17920
#define SMEM1  (3 * STG1 * 2 + 512)
#define SMEM2  (3 * STG2 * 2 + 512)

// ---------------------------------------------------------------------------
// FFN1: a = xWg, u = xWu, h = silu(a)*u -> fp16
// CTA 128 tok x 64 cols, 8 warps 32x32 (wm 4 x wn 2), K-chunk 64.
// ALSO converts a 2048-float slice of Wd (all 8192 CTAs, before early exit)
// so the Wd conversion overlaps the GEMM; ffn2 runs strictly after ffn1.
// ---------------------------------------------------------------------------
__global__ __launch_bounds__(256, 2) void ffn1_kernel(
        const float* __restrict__ wd_src) {
    extern __shared__ __align__(16) __half sm[];
    const int tid = threadIdx.x;

    // --- Wd conversion slice: 2048 floats per CTA = 8 per thread ---
    {
        size_t cta = (size_t)blockIdx.x +
                     (size_t)gridDim.x * (blockIdx.y + (size_t)gridDim.y * blockIdx.z);
        size_t base = cta * 2048 + (size_t)tid * 8;
        cvt8(wd_src + base, g_Wd + base);
    }

    const int e = blockIdx.z;
    const int cnt = g_cnt[e];
    const int row0 = blockIdx.x * 128;
    if (row0 >= cnt) return;
    const int col0 = blockIdx.y * 64;
    const int lane = tid & 31, wid = tid >> 5;
    const int wm = (wid & 3) * 32, wn = (wid >> 2) * 32;

    int* toks = (int*)(sm + 3 * STG1);
    if (tid < 128) {
        int r = row0 + tid;
        toks[tid] = (r < cnt) ? g_list[e][r] : -1;
    }
    __syncthreads();
    const uint32_t sbase = smem_to_u32(sm);

    const __half* aP[4];
    uint32_t szA[4], dA[4];
#pragma unroll
    for (int j = 0; j < 4; j++) {
        int idx = tid + j * 256;
        int r = idx >> 3, s = idx & 7;
        int t = toks[r];
        aP[j] = g_x + (size_t)(t < 0 ? 0 : t) * DIM + s * 8;
        szA[j] = (t >= 0) ? 16u : 0u;
        dA[j] = (uint32_t)(r * LDA + s * 8) * 2;
    }
    const __half *wgP[2], *wuP[2];
    uint32_t dB[2];
#pragma unroll
    for (int j = 0; j < 2; j++) {
        int idx = tid + j * 256;
        int rb = idx >> 3, sb_ = idx & 7;
        wgP[j] = g_Wg + (size_t)e * DIM * HID + (size_t)rb * HID + col0 + sb_ * 8;
        wuP[j] = g_Wu + (size_t)e * DIM * HID + (size_t)rb * HID + col0 + sb_ * 8;
        dB[j] = (uint32_t)(OFF_B + rb * LDB + sb_ * 8) * 2;
    }

    float accg[2][4][4], accu[2][4][4];
#pragma unroll
    for (int mt = 0; mt < 2; mt++)
#pragma unroll
        for (int nt = 0; nt < 4; nt++)
#pragma unroll
            for (int j = 0; j < 4; j++) { accg[mt][nt][j] = 0.f; accu[mt][nt][j] = 0.f; }

    const int NK = DIM / KC;   // 16

#pragma unroll
    for (int pc = 0; pc < 2; pc++) {
        int ko = pc * KC;
        uint32_t sb = sbase + (uint32_t)(pc * STG1 * 2);
#pragma unroll
        for (int j = 0; j < 4; j++) cp16(sb + dA[j], aP[j] + ko, szA[j]);
#pragma unroll
        for (int j = 0; j < 2; j++) {
            cp16(sb + dB[j],            wgP[j] + (size_t)ko * HID, 16);
            cp16(sb + dB[j] + BMAT * 2, wuP[j] + (size_t)ko * HID, 16);
        }
        CP_COMMIT();
    }

    const int lq = lane & 15, lh = lane >> 4;
    uint32_t aAddr = sbase + (uint32_t)((wm + lq) * LDA + 8 * lh) * 2;
    uint32_t bAddr = sbase + (uint32_t)(OFF_B + lq * LDB + wn + 8 * lh) * 2;

    int stage = 0;
    for (int i = 0; i < NK; i++) {
        CP_WAIT1();
        __syncthreads();

        if (i + 2 < NK) {
            int ko = (i + 2) * KC;
            int ps = stage + 2; if (ps >= 3) ps -= 3;
            uint32_t sb = sbase + (uint32_t)(ps * STG1 * 2);
#pragma unroll
            for (int j = 0; j < 4; j++) cp16(sb + dA[j], aP[j] + ko, szA[j]);
#pragma unroll
            for (int j = 0; j < 2; j++) {
                cp16(sb + dB[j],            wgP[j] + (size_t)ko * HID, 16);
                cp16(sb + dB[j] + BMAT * 2, wuP[j] + (size_t)ko * HID, 16);
            }
        }
        CP_COMMIT();

        uint32_t stg = (uint32_t)(stage * STG1 * 2);
#pragma unroll
        for (int ks = 0; ks < KC; ks += 16) {
            uint32_t a_[2][4];
#pragma unroll
            for (int mt = 0; mt < 2; mt++)
                ldsm_x4(a_[mt], aAddr + stg + (uint32_t)(mt * 16 * LDA + ks) * 2);
            uint32_t bg[2][4], bu[2][4];
#pragma unroll
            for (int nt2 = 0; nt2 < 2; nt2++) {
                uint32_t bd = bAddr + stg + (uint32_t)(ks * LDB + nt2 * 16) * 2;
                ldsm_x4t(bg[nt2], bd);
                ldsm_x4t(bu[nt2], bd + BMAT * 2);
            }
#pragma unroll
            for (int mt = 0; mt < 2; mt++)
#pragma unroll
                for (int nt = 0; nt < 4; nt++) {
                    uint32_t* pg = &bg[nt >> 1][(nt & 1) * 2];
                    uint32_t* pu = &bu[nt >> 1][(nt & 1) * 2];
                    MMA_F16(accg[mt][nt], a_[mt], pg[0], pg[1]);
                    MMA_F16(accu[mt][nt], a_[mt], pu[0], pu[1]);
                }
        }
        stage++; if (stage >= 3) stage = 0;
    }

    const int lr = lane >> 2, lk = (lane & 3) * 2;
#pragma unroll
    for (int mt = 0; mt < 2; mt++) {
        int ra = wm + mt * 16 + lr;
        int ta = toks[ra], tb = toks[ra + 8];
#pragma unroll
        for (int nt = 0; nt < 4; nt++) {
            int col = col0 + wn + nt * 8 + lk;
            if (ta >= 0) {
                float a0v = accg[mt][nt][0], a1v = accg[mt][nt][1];
                float u0v = accu[mt][nt][0], u1v = accu[mt][nt][1];
                float hv0 = a0v * u0v / (1.f + __expf(-a0v));
                float hv1 = a1v * u1v / (1.f + __expf(-a1v));
                *(__half2*)(g_h + (size_t)ta * HID + col) =
                    __halves2half2(__float2half_rn(hv0), __float2half_rn(hv1));
            }
            if (tb >= 0) {
                float a0v = accg[mt][nt][2], a1v = accg[mt][nt][3];
                float u0v = accu[mt][nt][2], u1v = accu[mt][nt][3];
                float hv0 = a0v * u0v / (1.f + __expf(-a0v));
                float hv1 = a1v * u1v / (1.f + __expf(-a1v));
                *(__half2*)(g_h + (size_t)tb * HID + col) =
                    __halves2half2(__float2half_rn(hv0), __float2half_rn(hv1));
            }
        }
    }
}

// ---------------------------------------------------------------------------
// FFN2: out = h Wd (fp32). CTA 128 x 128, 8 warps 32x64 (wm 4 x wn 2), K-chunk 64
// ---------------------------------------------------------------------------
__global__ __launch_bounds__(256, 2) void ffn2_kernel(float* __restrict__ out) {
    extern __shared__ __align__(16) __half sm[];
    const int e = blockIdx.z;
    const int cnt = g_cnt[e];
    const int row0 = blockIdx.x * 128;
    if (row0 >= cnt) return;
    const int col0 = blockIdx.y * 128;
    const int tid = threadIdx.x, lane = tid & 31, wid = tid >> 5;
    const int wm = (wid & 3) * 32, wn = (wid >> 2) * 64;

    int* toks = (int*)(sm + 3 * STG2);
    if (tid < 128) {
        int r = row0 + tid;
        toks[tid] = (r < cnt) ? g_list[e][r] : -1;
    }
    __syncthreads();
    const uint32_t sbase = smem_to_u32(sm);

    const __half* aP[4];
    uint32_t szA[4], dA[4];
#pragma unroll
    for (int j = 0; j < 4; j++) {
        int idx = tid + j * 256;
        int r = idx >> 3, s = idx & 7;
        int t = toks[r];
        aP[j] = g_h + (size_t)(t < 0 ? 0 : t) * HID + s * 8;
        szA[j] = (t >= 0) ? 16u : 0u;
        dA[j] = (uint32_t)(r * LDA + s * 8) * 2;
    }
    const __half* wdP[4];
    uint32_t dB[4];
#pragma unroll
    for (int j = 0; j < 4; j++) {
        int idx = tid + j * 256;
        int rb = idx >> 4, sb_ = idx & 15;
        wdP[j] = g_Wd + (size_t)e * HID * DIM + (size_t)rb * DIM + col0 + sb_ * 8;
        dB[j] = (uint32_t)(OFF_B + rb * LDB2 + sb_ * 8) * 2;
    }

    float acc[2][8][4];
#pragma unroll
    for (int mt = 0; mt < 2; mt++)
#pragma unroll
        for (int nt = 0; nt < 8; nt++)
#pragma unroll
            for (int j = 0; j < 4; j++) acc[mt][nt][j] = 0.f;

    const int NK = HID / KC;   // 32

#pragma unroll
    for (int pc = 0; pc < 2; pc++) {
        int ko = pc * KC;
        uint32_t sb = sbase + (uint32_t)(pc * STG2 * 2);
#pragma unroll
        for (int j = 0; j < 4; j++) cp16(sb + dA[j], aP[j] + ko, szA[j]);
#pragma unroll
        for (int j = 0; j < 4; j++) cp16(sb + dB[j], wdP[j] + (size_t)ko * DIM, 16);
        CP_COMMIT();
    }

    const int lq = lane & 15, lh = lane >> 4;
    uint32_t aAddr = sbase + (uint32_t)((wm + lq) * LDA + 8 * lh) * 2;
    uint32_t bAddr = sbase + (uint32_t)(OFF_B + lq * LDB2 + wn + 8 * lh) * 2;

    int stage = 0;
    for (int i = 0; i < NK; i++) {
        CP_WAIT1();
        __syncthreads();

        if (i + 2 < NK) {
            int ko = (i + 2) * KC;
            int ps = stage + 2; if (ps >= 3) ps -= 3;
            uint32_t sb = sbase + (uint32_t)(ps * STG2 * 2);
#pragma unroll
            for (int j = 0; j < 4; j++) cp16(sb + dA[j], aP[j] + ko, szA[j]);
#pragma unroll
            for (int j = 0; j < 4; j++) cp16(sb + dB[j], wdP[j] + (size_t)ko * DIM, 16);
        }
        CP_COMMIT();

        uint32_t stg = (uint32_t)(stage * STG2 * 2);
#pragma unroll
        for (int ks = 0; ks < KC; ks += 16) {
            uint32_t a_[2][4];
#pragma unroll
            for (int mt = 0; mt < 2; mt++)
                ldsm_x4(a_[mt], aAddr + stg + (uint32_t)(mt * 16 * LDA + ks) * 2);
            uint32_t bd_[4][4];
#pragma unroll
            for (int nt2 = 0; nt2 < 4; nt2++)
                ldsm_x4t(bd_[nt2], bAddr + stg + (uint32_t)(ks * LDB2 + nt2 * 16) * 2);
#pragma unroll
            for (int mt = 0; mt < 2; mt++)
#pragma unroll
                for (int nt = 0; nt < 8; nt++) {
                    uint32_t* pb = &bd_[nt >> 1][(nt & 1) * 2];
                    MMA_F16(acc[mt][nt], a_[mt], pb[0], pb[1]);
                }
        }
        stage++; if (stage >= 3) stage = 0;
    }

    const int lr = lane >> 2, lk = (lane & 3) * 2;
#pragma unroll
    for (int mt = 0; mt < 2; mt++) {
        int ra = wm + mt * 16 + lr;
        int ta = toks[ra], tb = toks[ra + 8];
#pragma unroll
        for (int nt = 0; nt < 8; nt++) {
            int col = col0 + wn + nt * 8 + lk;
            if (ta >= 0)
                *(float2*)(out + (size_t)ta * DIM + col) =
                    make_float2(acc[mt][nt][0], acc[mt][nt][1]);
            if (tb >= 0)
                *(float2*)(out + (size_t)tb * DIM + col) =
                    make_float2(acc[mt][nt][2], acc[mt][nt][3]);
        }
    }
}

// ---------------------------------------------------------------------------
extern "C" void kernel_launch(void* const* d_in, const int* in_sizes, int n_in,
                              void* d_out, int out_size) {
    const float* x         = (const float*)d_in[0];
    const float* gate_w    = (const float*)d_in[1];
    const float* gate_bank = (const float*)d_in[2];
    const float* up_bank   = (const float*)d_in[3];
    const float* down_bank = (const float*)d_in[4];
    float* out = (float*)d_out;

    cudaFuncSetAttribute(ffn1_kernel,
                         cudaFuncAttributeMaxDynamicSharedMemorySize, SMEM1);
    cudaFuncSetAttribute(ffn2_kernel,
                         cudaFuncAttributeMaxDynamicSharedMemorySize, SMEM2);

    init_kernel<<<1, 32>>>();
    gate_convert_kernel<<<BT, 256>>>(x, gate_w, gate_bank, up_bank);
    ffn1_kernel<<<dim3(BT / 128, HID / 64, NEXP), 256, SMEM1>>>(down_bank);
    ffn2_kernel<<<dim3(BT / 128, DIM / 128, NEXP), 256, SMEM2>>>(out);
}

// round 12
// speedup vs baseline: 6.2178x; 1.0244x over previous
#include <cuda_runtime.h>
#include <cuda_fp16.h>
#include <cstdint>

#define BT   4096
#define DIM  1024
#define NEXP 8
#define HID  2048

#define XSZ  ((size_t)BT * DIM)
#define HSZ  ((size_t)BT * HID)
#define WSZ  ((size_t)NEXP * HID * DIM)

// ---------------------------------------------------------------------------
__device__ int g_cnt[NEXP];
__device__ int g_list[NEXP][BT];
__device__ __align__(16) __half g_x[XSZ];
__device__ __align__(16) __half g_h[HSZ];
__device__ __align__(16) __half g_Wg[WSZ];
__device__ __align__(16) __half g_Wu[WSZ];
__device__ __align__(16) __half g_Wd[WSZ];

// ---------------------------------------------------------------------------
__device__ __forceinline__ uint32_t smem_to_u32(const void* smem_ptr) {
    uint32_t addr;
    asm("{ .reg .u64 tmp; cvta.to.shared.u64 tmp, %1; cvt.u32.u64 %0, tmp; }"
        : "=r"(addr) : "l"(smem_ptr));
    return addr;
}

__device__ __forceinline__ void cp16(uint32_t dst, const void* src, uint32_t sz) {
    asm volatile("cp.async.cg.shared.global [%0], [%1], 16, %2;\n"
                 :: "r"(dst), "l"(src), "r"(sz));
}
#define CP_COMMIT() asm volatile("cp.async.commit_group;\n" ::: "memory")
#define CP_WAIT1()  asm volatile("cp.async.wait_group 1;\n" ::: "memory")

__device__ __forceinline__ void ldsm_x4(uint32_t* r, uint32_t addr) {
    asm volatile("ldmatrix.sync.aligned.m8n8.x4.shared.b16 {%0,%1,%2,%3}, [%4];"
        : "=r"(r[0]), "=r"(r[1]), "=r"(r[2]), "=r"(r[3]) : "r"(addr));
}
__device__ __forceinline__ void ldsm_x4t(uint32_t* r, uint32_t addr) {
    asm volatile("ldmatrix.sync.aligned.m8n8.x4.trans.shared.b16 {%0,%1,%2,%3}, [%4];"
        : "=r"(r[0]), "=r"(r[1]), "=r"(r[2]), "=r"(r[3]) : "r"(addr));
}

#define MMA_F16(acc, a, b0, b1) \
    asm volatile("mma.sync.aligned.m16n8k16.row.col.f32.f16.f16.f32 " \
        "{%0,%1,%2,%3}, {%4,%5,%6,%7}, {%8,%9}, {%0,%1,%2,%3};" \
        : "+f"((acc)[0]), "+f"((acc)[1]), "+f"((acc)[2]), "+f"((acc)[3]) \
        : "r"((a)[0]), "r"((a)[1]), "r"((a)[2]), "r"((a)[3]), \
          "r"(b0), "r"(b1))

// convert 8 consecutive floats -> 8 halves (one uint4 store)
__device__ __forceinline__ void cvt8(const float* __restrict__ s,
                                     __half* __restrict__ d) {
    float4 v0 = *(const float4*)s;
    float4 v1 = *(const float4*)(s + 4);
    __half h[8];
    h[0] = __float2half_rn(v0.x); h[1] = __float2half_rn(v0.y);
    h[2] = __float2half_rn(v0.z); h[3] = __float2half_rn(v0.w);
    h[4] = __float2half_rn(v1.x); h[5] = __float2half_rn(v1.y);
    h[6] = __float2half_rn(v1.z); h[7] = __float2half_rn(v1.w);
    *(uint4*)d = *(uint4*)h;
}

// ---------------------------------------------------------------------------
__global__ void init_kernel() {
    if (threadIdx.x < NEXP) g_cnt[threadIdx.x] = 0;
}

// ---------------------------------------------------------------------------
// Fused: x convert (fp16) + gating + scatter + Wg/Wu fp32->fp16 conversion.
// ---------------------------------------------------------------------------
__global__ __launch_bounds__(256) void gate_convert_kernel(
        const float* __restrict__ x, const float* __restrict__ gw,
        const float* __restrict__ wg_src, const float* __restrict__ wu_src) {
    __shared__ float red[8][8];
    __shared__ float logits[8];
    const int t = blockIdx.x;
    const int tid = threadIdx.x;
    const int lane = tid & 31, wid = tid >> 5;

    float4 v = ((const float4*)x)[(size_t)t * (DIM / 4) + tid];

    __half2 p0 = __halves2half2(__float2half_rn(v.x), __float2half_rn(v.y));
    __half2 p1 = __halves2half2(__float2half_rn(v.z), __float2half_rn(v.w));
    size_t o = (size_t)t * DIM + tid * 4;
    *(__half2*)(g_x + o)     = p0;
    *(__half2*)(g_x + o + 2) = p1;

    float acc[NEXP];
#pragma unroll
    for (int e = 0; e < NEXP; e++) {
        float4 g = ((const float4*)(gw + (size_t)e * DIM))[tid];
        acc[e] = v.x * g.x + v.y * g.y + v.z * g.z + v.w * g.w;
    }
#pragma unroll
    for (int e = 0; e < NEXP; e++) {
#pragma unroll
        for (int off = 16; off > 0; off >>= 1)
            acc[e] += __shfl_xor_sync(0xffffffffu, acc[e], off);
    }
    if (lane == 0) {
#pragma unroll
        for (int e = 0; e < NEXP; e++) red[wid][e] = acc[e];
    }
    __syncthreads();
    if (tid < 8) {
        float s = 0.f;
#pragma unroll
        for (int w = 0; w < 8; w++) s += red[w][tid];
        logits[tid] = s;
    }
    __syncthreads();
    if (tid == 0) {
        int best = 0; float bv = logits[0];
#pragma unroll
        for (int e = 1; e < NEXP; e++)
            if (logits[e] > bv) { bv = logits[e]; best = e; }
        int p = atomicAdd(&g_cnt[best], 1);
        g_list[best][p] = t;
    }

    {
        size_t base = (size_t)t * 4096 + (size_t)tid * 16;
        cvt8(wg_src + base,     g_Wg + base);
        cvt8(wg_src + base + 8, g_Wg + base + 8);
        cvt8(wu_src + base,     g_Wu + base);
        cvt8(wu_src + base + 8, g_Wu + base + 8);
    }
}

// ---------------------------------------------------------------------------
// smem geometry (halves). K-chunk = 64, 3 stages.
// ---------------------------------------------------------------------------
#define KC     64
#define LDA    72
#define LDB    72
#define LDB2   136
#define OFF_B  9216
#define BMAT   (64 * LDB)              // 4608 halves
#define STG1   (OFF_B + 2 * BMAT)      // 18432
#define STG2   (OFF_B + 64 * LDB2)     // 17920
#define SMEM1  (3 * STG1 * 2 + 512)
#define SMEM2  (3 * STG2 * 2 + 512)

// ---------------------------------------------------------------------------
// FFN1: a = xWg, u = xWu, h = silu(a)*u -> fp16
// CTA 128 tok x 64 cols, 8 warps 32x32 (wm 4 x wn 2), K-chunk 64.
// Register-level fragment pipeline: A/Bg double-buffered one k16 group ahead;
// Bu single-buffered (latency hidden by the gate MMA burst).
// Also converts a 2048-float slice of Wd before the early-exit (overlap).
// ---------------------------------------------------------------------------
__global__ __launch_bounds__(256, 2) void ffn1_kernel(
        const float* __restrict__ wd_src) {
    extern __shared__ __align__(16) __half sm[];
    const int tid = threadIdx.x;

    {
        size_t cta = (size_t)blockIdx.x +
                     (size_t)gridDim.x * (blockIdx.y + (size_t)gridDim.y * blockIdx.z);
        size_t base = cta * 2048 + (size_t)tid * 8;
        cvt8(wd_src + base, g_Wd + base);
    }

    const int e = blockIdx.z;
    const int cnt = g_cnt[e];
    const int row0 = blockIdx.x * 128;
    if (row0 >= cnt) return;
    const int col0 = blockIdx.y * 64;
    const int lane = tid & 31, wid = tid >> 5;
    const int wm = (wid & 3) * 32, wn = (wid >> 2) * 32;

    int* toks = (int*)(sm + 3 * STG1);
    if (tid < 128) {
        int r = row0 + tid;
        toks[tid] = (r < cnt) ? g_list[e][r] : -1;
    }
    __syncthreads();
    const uint32_t sbase = smem_to_u32(sm);
    const size_t wbase = (size_t)e * DIM * HID + col0;

    // issue one K-chunk (addresses recomputed each call; toks in smem)
    auto issue = [&](int ko, uint32_t sb) {
#pragma unroll
        for (int j = 0; j < 4; j++) {
            int idx = tid + j * 256;
            int r = idx >> 3, s = idx & 7;
            int t = toks[r];
            const __half* ap = g_x + (size_t)(t < 0 ? 0 : t) * DIM + ko + s * 8;
            cp16(sb + (uint32_t)(r * LDA + s * 8) * 2, ap, t >= 0 ? 16u : 0u);
        }
#pragma unroll
        for (int j = 0; j < 2; j++) {
            int idx = tid + j * 256;
            int rb = idx >> 3, sbk = idx & 7;
            size_t w = wbase + (size_t)(ko + rb) * HID + sbk * 8;
            uint32_t d = sb + (uint32_t)(OFF_B + rb * LDB + sbk * 8) * 2;
            cp16(d,            g_Wg + w, 16);
            cp16(d + BMAT * 2, g_Wu + w, 16);
        }
    };

    float accg[2][4][4], accu[2][4][4];
#pragma unroll
    for (int mt = 0; mt < 2; mt++)
#pragma unroll
        for (int nt = 0; nt < 4; nt++)
#pragma unroll
            for (int j = 0; j < 4; j++) { accg[mt][nt][j] = 0.f; accu[mt][nt][j] = 0.f; }

    const int lq = lane & 15, lh = lane >> 4;
    const uint32_t aAddr = sbase + (uint32_t)((wm + lq) * LDA + 8 * lh) * 2;
    const uint32_t bAddr = sbase + (uint32_t)(OFF_B + lq * LDB + wn + 8 * lh) * 2;

    uint32_t aF[2][2][4], bgF[2][2][4], buF[2][4];

    auto ldA = [&](int set, uint32_t stg, int ks) {
#pragma unroll
        for (int mt = 0; mt < 2; mt++)
            ldsm_x4(aF[set][mt], aAddr + stg + (uint32_t)(mt * 16 * LDA + ks) * 2);
    };
    auto ldBg = [&](int set, uint32_t stg, int ks) {
#pragma unroll
        for (int n2 = 0; n2 < 2; n2++)
            ldsm_x4t(bgF[set][n2], bAddr + stg + (uint32_t)(ks * LDB + n2 * 16) * 2);
    };
    auto ldBu = [&](uint32_t stg, int ks) {
#pragma unroll
        for (int n2 = 0; n2 < 2; n2++)
            ldsm_x4t(buF[n2], bAddr + stg + (uint32_t)(ks * LDB + n2 * 16) * 2 + BMAT * 2);
    };
    auto mmas = [&](int set) {
#pragma unroll
        for (int mt = 0; mt < 2; mt++)
#pragma unroll
            for (int nt = 0; nt < 4; nt++) {
                uint32_t* pg = &bgF[set][nt >> 1][(nt & 1) * 2];
                MMA_F16(accg[mt][nt], aF[set][mt], pg[0], pg[1]);
            }
#pragma unroll
        for (int mt = 0; mt < 2; mt++)
#pragma unroll
            for (int nt = 0; nt < 4; nt++) {
                uint32_t* pu = &buF[nt >> 1][(nt & 1) * 2];
                MMA_F16(accu[mt][nt], aF[set][mt], pu[0], pu[1]);
            }
    };

    const int NK = DIM / KC;   // 16

    // prologue: chunks 0 and 1 in flight; chunk 0 complete before first barrier
    issue(0, sbase);            CP_COMMIT();
    issue(KC, sbase + STG1 * 2); CP_COMMIT();
    CP_WAIT1();

    int stage = 0;
    for (int i = 0; i < NK; i++) {
        __syncthreads();   // chunk i visible to all; stage (i-1)%3 free for reuse

        // group-0 fragments; their latency overlaps the cp.async issue below
        ldA(0, (uint32_t)(stage * STG1 * 2), 0);
        ldBg(0, (uint32_t)(stage * STG1 * 2), 0);

        if (i + 2 < NK) {
            int ps = stage + 2; if (ps >= 3) ps -= 3;
            issue((i + 2) * KC, sbase + (uint32_t)(ps * STG1 * 2));
        }
        CP_COMMIT();

        uint32_t stg = (uint32_t)(stage * STG1 * 2);
#pragma unroll
        for (int g = 0; g < 4; g++) {
            const int cur = g & 1;
            ldBu(stg, g * 16);                       // hidden by gate burst
            if (g < 3) {                             // prefetch next group
                ldA(cur ^ 1, stg, (g + 1) * 16);
                ldBg(cur ^ 1, stg, (g + 1) * 16);
            }
            mmas(cur);
        }
        CP_WAIT1();        // chunk i+1 complete before next barrier
        stage++; if (stage >= 3) stage = 0;
    }

    const int lr = lane >> 2, lk = (lane & 3) * 2;
#pragma unroll
    for (int mt = 0; mt < 2; mt++) {
        int ra = wm + mt * 16 + lr;
        int ta = toks[ra], tb = toks[ra + 8];
#pragma unroll
        for (int nt = 0; nt < 4; nt++) {
            int col = col0 + wn + nt * 8 + lk;
            if (ta >= 0) {
                float a0v = accg[mt][nt][0], a1v = accg[mt][nt][1];
                float u0v = accu[mt][nt][0], u1v = accu[mt][nt][1];
                float hv0 = a0v * u0v / (1.f + __expf(-a0v));
                float hv1 = a1v * u1v / (1.f + __expf(-a1v));
                *(__half2*)(g_h + (size_t)ta * HID + col) =
                    __halves2half2(__float2half_rn(hv0), __float2half_rn(hv1));
            }
            if (tb >= 0) {
                float a0v = accg[mt][nt][2], a1v = accg[mt][nt][3];
                float u0v = accu[mt][nt][2], u1v = accu[mt][nt][3];
                float hv0 = a0v * u0v / (1.f + __expf(-a0v));
                float hv1 = a1v * u1v / (1.f + __expf(-a1v));
                *(__half2*)(g_h + (size_t)tb * HID + col) =
                    __halves2half2(__float2half_rn(hv0), __float2half_rn(hv1));
            }
        }
    }
}

// ---------------------------------------------------------------------------
// FFN2: out = h Wd (fp32). CTA 128 x 128, 8 warps 32x64 (wm 4 x wn 2),
// K-chunk 64, full A+B fragment double-buffering.
// ---------------------------------------------------------------------------
__global__ __launch_bounds__(256, 2) void ffn2_kernel(float* __restrict__ out) {
    extern __shared__ __align__(16) __half sm[];
    const int e = blockIdx.z;
    const int cnt = g_cnt[e];
    const int row0 = blockIdx.x * 128;
    if (row0 >= cnt) return;
    const int col0 = blockIdx.y * 128;
    const int tid = threadIdx.x, lane = tid & 31, wid = tid >> 5;
    const int wm = (wid & 3) * 32, wn = (wid >> 2) * 64;

    int* toks = (int*)(sm + 3 * STG2);
    if (tid < 128) {
        int r = row0 + tid;
        toks[tid] = (r < cnt) ? g_list[e][r] : -1;
    }
    __syncthreads();
    const uint32_t sbase = smem_to_u32(sm);
    const size_t wbase = (size_t)e * HID * DIM + col0;

    auto issue = [&](int ko, uint32_t sb) {
#pragma unroll
        for (int j = 0; j < 4; j++) {
            int idx = tid + j * 256;
            int r = idx >> 3, s = idx & 7;
            int t = toks[r];
            const __half* ap = g_h + (size_t)(t < 0 ? 0 : t) * HID + ko + s * 8;
            cp16(sb + (uint32_t)(r * LDA + s * 8) * 2, ap, t >= 0 ? 16u : 0u);
        }
#pragma unroll
        for (int j = 0; j < 4; j++) {
            int idx = tid + j * 256;
            int rb = idx >> 4, sbk = idx & 15;
            size_t w = wbase + (size_t)(ko + rb) * DIM + sbk * 8;
            cp16(sb + (uint32_t)(OFF_B + rb * LDB2 + sbk * 8) * 2, g_Wd + w, 16);
        }
    };

    float acc[2][8][4];
#pragma unroll
    for (int mt = 0; mt < 2; mt++)
#pragma unroll
        for (int nt = 0; nt < 8; nt++)
#pragma unroll
            for (int j = 0; j < 4; j++) acc[mt][nt][j] = 0.f;

    const int lq = lane & 15, lh = lane >> 4;
    const uint32_t aAddr = sbase + (uint32_t)((wm + lq) * LDA + 8 * lh) * 2;
    const uint32_t bAddr = sbase + (uint32_t)(OFF_B + lq * LDB2 + wn + 8 * lh) * 2;

    uint32_t aF[2][2][4], bF[2][4][4];

    auto ldA = [&](int set, uint32_t stg, int ks) {
#pragma unroll
        for (int mt = 0; mt < 2; mt++)
            ldsm_x4(aF[set][mt], aAddr + stg + (uint32_t)(mt * 16 * LDA + ks) * 2);
    };
    auto ldB = [&](int set, uint32_t stg, int ks) {
#pragma unroll
        for (int n2 = 0; n2 < 4; n2++)
            ldsm_x4t(bF[set][n2], bAddr + stg + (uint32_t)(ks * LDB2 + n2 * 16) * 2);
    };
    auto mmas = [&](int set) {
#pragma unroll
        for (int mt = 0; mt < 2; mt++)
#pragma unroll
            for (int nt = 0; nt < 8; nt++) {
                uint32_t* pb = &bF[set][nt >> 1][(nt & 1) * 2];
                MMA_F16(acc[mt][nt], aF[set][mt], pb[0], pb[1]);
            }
    };

    const int NK = HID / KC;   // 32

    issue(0, sbase);            CP_COMMIT();
    issue(KC, sbase + STG2 * 2); CP_COMMIT();
    CP_WAIT1();

    int stage = 0;
    for (int i = 0; i < NK; i++) {
        __syncthreads();

        ldA(0, (uint32_t)(stage * STG2 * 2), 0);
        ldB(0, (uint32_t)(stage * STG2 * 2), 0);

        if (i + 2 < NK) {
            int ps = stage + 2; if (ps >= 3) ps -= 3;
            issue((i + 2) * KC, sbase + (uint32_t)(ps * STG2 * 2));
        }
        CP_COMMIT();

        uint32_t stg = (uint32_t)(stage * STG2 * 2);
#pragma unroll
        for (int g = 0; g < 4; g++) {
            const int cur = g & 1;
            if (g < 3) {
                ldA(cur ^ 1, stg, (g + 1) * 16);
                ldB(cur ^ 1, stg, (g + 1) * 16);
            }
            mmas(cur);
        }
        CP_WAIT1();
        stage++; if (stage >= 3) stage = 0;
    }

    const int lr = lane >> 2, lk = (lane & 3) * 2;
#pragma unroll
    for (int mt = 0; mt < 2; mt++) {
        int ra = wm + mt * 16 + lr;
        int ta = toks[ra], tb = toks[ra + 8];
#pragma unroll
        for (int nt = 0; nt < 8; nt++) {
            int col = col0 + wn + nt * 8 + lk;
            if (ta >= 0)
                *(float2*)(out + (size_t)ta * DIM + col) =
                    make_float2(acc[mt][nt][0], acc[mt][nt][1]);
            if (tb >= 0)
                *(float2*)(out + (size_t)tb * DIM + col) =
                    make_float2(acc[mt][nt][2], acc[mt][nt][3]);
        }
    }
}

// ---------------------------------------------------------------------------
extern "C" void kernel_launch(void* const* d_in, const int* in_sizes, int n_in,
                              void* d_out, int out_size) {
    const float* x         = (const float*)d_in[0];
    const float* gate_w    = (const float*)d_in[1];
    const float* gate_bank = (const float*)d_in[2];
    const float* up_bank   = (const float*)d_in[3];
    const float* down_bank = (const float*)d_in[4];
    float* out = (float*)d_out;

    cudaFuncSetAttribute(ffn1_kernel,
                         cudaFuncAttributeMaxDynamicSharedMemorySize, SMEM1);
    cudaFuncSetAttribute(ffn2_kernel,
                         cudaFuncAttributeMaxDynamicSharedMemorySize, SMEM2);

    init_kernel<<<1, 32>>>();
    gate_convert_kernel<<<BT, 256>>>(x, gate_w, gate_bank, up_bank);
    ffn1_kernel<<<dim3(BT / 128, HID / 64, NEXP), 256, SMEM1>>>(down_bank);
    ffn2_kernel<<<dim3(BT / 128, DIM / 128, NEXP), 256, SMEM2>>>(out);
}